// round 1
// baseline (speedup 1.0000x reference)
#include <cuda_runtime.h>
#include <cuda_bf16.h>

// Problem constants
#define BB    4
#define TT    2048
#define DM    1024
#define HQ    16
#define HKV   4
#define HD    64
#define MROWS (BB*TT)          // 8192

// Scratch (device globals; allocation-free contract)
__device__ float g_q [BB*HQ *TT*HD];   // (b,h,t,d)   32 MB
__device__ float g_k [BB*HKV*TT*HD];   // (b,hk,t,d)   8 MB
__device__ float g_v [BB*HKV*TT*HD];   //              8 MB
__device__ float g_ao[BB*TT*DM];       // (b,t,h*d)   32 MB

// ---------------------------------------------------------------------------
// Tiled SGEMM: C[M,N] = A[M,K] @ W[K,N]; 128x128 block, BK=8, 256 threads,
// 8x8 microtile per thread. MODE selects epilogue:
//   0: plain row-major store to C
//   1: Q projection -> RoPE -> g_q[(b*HQ+h), t, d]
//   2: KV projection -> split; K gets RoPE -> g_k / g_v [(b*HKV+hk), t, d]
// All dims assumed multiples of tile sizes (they are: 8192/1024/512/1024).
// ---------------------------------------------------------------------------
template <int MODE>
__global__ __launch_bounds__(256)
void gemm128(const float* __restrict__ A, const float* __restrict__ W,
             float* __restrict__ C, int M, int N, int K,
             const float* __restrict__ cosb, const float* __restrict__ sinb)
{
    __shared__ float As[8][128];
    __shared__ float Bs[8][128];

    const int tid = threadIdx.x;
    const int tx  = tid & 15;          // col group
    const int ty  = tid >> 4;          // row group
    const int bm  = blockIdx.y * 128;
    const int bn  = blockIdx.x * 128;

    // loader indices
    const int ar = tid >> 1;           // 0..127  (A row within tile)
    const int ac = (tid & 1) * 4;      // 0 or 4  (A col group)
    const int br = tid >> 5;           // 0..7    (W row within tile)
    const int bc = (tid & 31) * 4;     // 0..124  (W col group)

    float acc[8][8];
#pragma unroll
    for (int i = 0; i < 8; i++)
#pragma unroll
        for (int j = 0; j < 8; j++) acc[i][j] = 0.f;

    for (int kt = 0; kt < K; kt += 8) {
        float4 av = *(const float4*)(A + (size_t)(bm + ar) * K + kt + ac);
        As[ac + 0][ar] = av.x;
        As[ac + 1][ar] = av.y;
        As[ac + 2][ar] = av.z;
        As[ac + 3][ar] = av.w;
        *(float4*)&Bs[br][bc] =
            *(const float4*)(W + (size_t)(kt + br) * N + bn + bc);
        __syncthreads();

#pragma unroll
        for (int k = 0; k < 8; k++) {
            float4 a0 = *(const float4*)&As[k][ty * 8];
            float4 a1 = *(const float4*)&As[k][ty * 8 + 4];
            float4 b0 = *(const float4*)&Bs[k][tx * 8];
            float4 b1 = *(const float4*)&Bs[k][tx * 8 + 4];
            float a[8] = {a0.x, a0.y, a0.z, a0.w, a1.x, a1.y, a1.z, a1.w};
            float b[8] = {b0.x, b0.y, b0.z, b0.w, b1.x, b1.y, b1.z, b1.w};
#pragma unroll
            for (int i = 0; i < 8; i++)
#pragma unroll
                for (int j = 0; j < 8; j++)
                    acc[i][j] = fmaf(a[i], b[j], acc[i][j]);
        }
        __syncthreads();
    }

    // Epilogue
#pragma unroll
    for (int i = 0; i < 8; i++) {
        const int mrow = bm + ty * 8 + i;
        if (MODE == 0) {
            float* crow = C + (size_t)mrow * N + bn + tx * 8;
            float4 o0 = {acc[i][0], acc[i][1], acc[i][2], acc[i][3]};
            float4 o1 = {acc[i][4], acc[i][5], acc[i][6], acc[i][7]};
            *(float4*)(crow)     = o0;
            *(float4*)(crow + 4) = o1;
        } else {
            const int b = mrow >> 11;            // / TT
            const int t = mrow & (TT - 1);
#pragma unroll
            for (int j = 0; j < 8; j += 2) {
                const int n  = bn + tx * 8 + j;
                const float v0 = acc[i][j];
                const float v1 = acc[i][j + 1];
                if (MODE == 1) {
                    const int h = n >> 6;
                    const int d = n & 63;
                    const float c  = cosb[t * HD + d];
                    const float sn = sinb[t * HD + d];
                    float* dst = &g_q[(((size_t)(b * HQ + h) * TT + t) << 6) + d];
                    dst[0] = v0 * c - v1 * sn;
                    dst[1] = v1 * c + v0 * sn;
                } else {
                    const int hk   = n >> 7;
                    const int pair = (n >> 6) & 1;
                    const int d    = n & 63;
                    const size_t idx = (((size_t)(b * HKV + hk) * TT + t) << 6) + d;
                    if (pair == 0) {
                        const float c  = cosb[t * HD + d];
                        const float sn = sinb[t * HD + d];
                        g_k[idx]     = v0 * c - v1 * sn;
                        g_k[idx + 1] = v1 * c + v0 * sn;
                    } else {
                        g_v[idx]     = v0;
                        g_v[idx + 1] = v1;
                    }
                }
            }
        }
    }
}

// ---------------------------------------------------------------------------
// Attention: grid (BB*HQ, TT/128), block 128. One thread owns one query row
// (q[64] + acc[64] in registers), online softmax over K/V tiles of 32 rows
// staged in shared memory. All smem reads in the compute loops are broadcast.
// ---------------------------------------------------------------------------
__global__ __launch_bounds__(128)
void attn_kernel()
{
    __shared__ float Ks[32 * 64];
    __shared__ float Vs[32 * 64];

    const int bh = blockIdx.x;           // b*HQ + h
    const int b  = bh >> 4;
    const int h  = bh & 15;
    const int hk = h >> 2;
    const int t  = blockIdx.y * 128 + threadIdx.x;

    const float* qrow = g_q + (((size_t)bh * TT + t) << 6);
    float q[64];
#pragma unroll
    for (int u = 0; u < 16; u++) {
        float4 v = ((const float4*)qrow)[u];
        q[4*u+0] = v.x; q[4*u+1] = v.y; q[4*u+2] = v.z; q[4*u+3] = v.w;
    }

    const float* kbase = g_k + (((size_t)(b * HKV + hk) * TT) << 6);
    const float* vbase = g_v + (((size_t)(b * HKV + hk) * TT) << 6);

    float acc[64];
#pragma unroll
    for (int d = 0; d < 64; d++) acc[d] = 0.f;
    float m = -3.0e38f;
    float l = 0.f;

    const float scale = 0.125f;          // 64^-0.5

    for (int kt = 0; kt < TT; kt += 32) {
        // cooperative tile load (coalesced float4)
        const float4* ksrc = (const float4*)(kbase + (size_t)kt * 64);
        const float4* vsrc = (const float4*)(vbase + (size_t)kt * 64);
#pragma unroll
        for (int i = 0; i < 4; i++) {
            int idx = threadIdx.x + i * 128;  // 0..511 float4s
            ((float4*)Ks)[idx] = ksrc[idx];
            ((float4*)Vs)[idx] = vsrc[idx];
        }
        __syncthreads();

        float s[32];
        float tmax = -3.0e38f;
#pragma unroll 4
        for (int j = 0; j < 32; j++) {
            const float4* kr = (const float4*)(Ks + j * 64);
            float sum = 0.f;
#pragma unroll
            for (int u = 0; u < 16; u++) {
                float4 kv = kr[u];
                sum = fmaf(q[4*u+0], kv.x, sum);
                sum = fmaf(q[4*u+1], kv.y, sum);
                sum = fmaf(q[4*u+2], kv.z, sum);
                sum = fmaf(q[4*u+3], kv.w, sum);
            }
            s[j] = sum * scale;
            tmax = fmaxf(tmax, s[j]);
        }

        const float nm   = fmaxf(m, tmax);
        const float corr = __expf(m - nm);
        l *= corr;
#pragma unroll
        for (int d = 0; d < 64; d++) acc[d] *= corr;

#pragma unroll 2
        for (int j = 0; j < 32; j++) {
            const float p = __expf(s[j] - nm);
            l += p;
            const float4* vr = (const float4*)(Vs + j * 64);
#pragma unroll
            for (int u = 0; u < 16; u++) {
                float4 vv = vr[u];
                acc[4*u+0] = fmaf(p, vv.x, acc[4*u+0]);
                acc[4*u+1] = fmaf(p, vv.y, acc[4*u+1]);
                acc[4*u+2] = fmaf(p, vv.z, acc[4*u+2]);
                acc[4*u+3] = fmaf(p, vv.w, acc[4*u+3]);
            }
        }
        m = nm;
        __syncthreads();
    }

    const float inv = 1.f / l;
    float* dst = g_ao + ((size_t)(b * TT + t) * DM) + h * HD;
#pragma unroll
    for (int u = 0; u < 16; u++) {
        float4 o = {acc[4*u+0] * inv, acc[4*u+1] * inv,
                    acc[4*u+2] * inv, acc[4*u+3] * inv};
        ((float4*)dst)[u] = o;
    }
}

// ---------------------------------------------------------------------------
extern "C" void kernel_launch(void* const* d_in, const int* in_sizes, int n_in,
                              void* d_out, int out_size)
{
    const float* x    = (const float*)d_in[0];
    const float* cosb = (const float*)d_in[1];
    const float* sinb = (const float*)d_in[2];
    const float* Wq   = (const float*)d_in[3];
    const float* Wkv  = (const float*)d_in[4];
    const float* Wo   = (const float*)d_in[5];
    float* out = (float*)d_out;

    void* p_ao = nullptr;
    cudaGetSymbolAddress(&p_ao, g_ao);

    // Q projection + RoPE
    {
        dim3 grid(DM / 128, MROWS / 128);
        gemm128<1><<<grid, 256>>>(x, Wq, nullptr, MROWS, DM, DM, cosb, sinb);
    }
    // KV projection + split + RoPE(K)
    {
        dim3 grid((2 * HKV * HD) / 128, MROWS / 128);
        gemm128<2><<<grid, 256>>>(x, Wkv, nullptr, MROWS, 2 * HKV * HD, DM,
                                  cosb, sinb);
    }
    // Attention
    {
        dim3 grid(BB * HQ, TT / 128);
        attn_kernel<<<grid, 128>>>();
    }
    // Output projection
    {
        dim3 grid(DM / 128, MROWS / 128);
        gemm128<0><<<grid, 256>>>((const float*)p_ao, Wo, out, MROWS, DM, DM,
                                  nullptr, nullptr);
    }
}

// round 3
// speedup vs baseline: 3.7051x; 3.7051x over previous
#include <cuda_runtime.h>
#include <cstdint>

#define BB    4
#define TT    2048
#define DM    1024
#define HQ    16
#define HKV   4
#define HD    64
#define MROWS (BB*TT)

// Scratch (device globals)
__device__ float g_q [BB*HQ *TT*HD];    // (b*HQ+h, t, d)
__device__ float g_k [BB*HKV*TT*HD];    // (b*HKV+hk, t, d)
__device__ float g_vt[BB*HKV*HD*TT];    // (b*HKV+hk, d, t)  -- transposed V
__device__ float g_ao[BB*TT*DM];        // (b, t, h*64+d)

// ---------------------------------------------------------------------------
__device__ __forceinline__ uint32_t f2tf(float f) {
    uint32_t r; asm("cvt.rna.tf32.f32 %0, %1;" : "=r"(r) : "f"(f)); return r;
}
__device__ __forceinline__ float ex2(float x) {
    float r; asm("ex2.approx.f32 %0, %1;" : "=f"(r) : "f"(x)); return r;
}
// D += A(m16 k8, tf32) * B(k8 n8, tf32)
__device__ __forceinline__ void mma8(float* d, const uint32_t* a, const uint32_t* b) {
    asm volatile(
        "mma.sync.aligned.m16n8k8.row.col.f32.tf32.tf32.f32 "
        "{%0,%1,%2,%3}, {%4,%5,%6,%7}, {%8,%9}, {%0,%1,%2,%3};"
        : "+f"(d[0]), "+f"(d[1]), "+f"(d[2]), "+f"(d[3])
        : "r"(a[0]), "r"(a[1]), "r"(a[2]), "r"(a[3]), "r"(b[0]), "r"(b[1]));
}

// ---------------------------------------------------------------------------
// tf32 mma GEMM: C[M,N] = A[M,K] @ W[K,N]. 128x128 tile, BK=16, 256 threads.
// 8 warps arranged 2(M) x 4(N); warp tile 64x32.
// MODE: 0 plain store, 1 Q+RoPE -> g_q, 2 KV split (K RoPE -> g_k, V -> g_vt).
// ---------------------------------------------------------------------------
template <int MODE>
__global__ __launch_bounds__(256)
void tcmm(const float* __restrict__ A, const float* __restrict__ W,
          float* __restrict__ C, int N, int K,
          const float* __restrict__ cosb, const float* __restrict__ sinb)
{
    __shared__ __align__(16) uint32_t sA[128 * 20];   // [m][k], stride 20
    __shared__ __align__(16) uint32_t sB[16 * 132];   // [k][n], stride 132

    const int tid  = threadIdx.x;
    const int lane = tid & 31, g = lane >> 2, t = lane & 3;
    const int wid  = tid >> 5, wm = wid >> 2, wn = wid & 3;
    const int bm   = blockIdx.y * 128, bn = blockIdx.x * 128;

    float acc[4][4][4] = {};

    for (int kt = 0; kt < K; kt += 16) {
        // A tile [128m][16k]
#pragma unroll
        for (int i = 0; i < 2; i++) {
            int idx = tid + i * 256;
            int m = idx >> 2, k4 = (idx & 3) * 4;
            float4 v = *(const float4*)(A + (size_t)(bm + m) * K + kt + k4);
            *(uint4*)&sA[m * 20 + k4] =
                make_uint4(f2tf(v.x), f2tf(v.y), f2tf(v.z), f2tf(v.w));
        }
        // B tile [16k][128n] (gmem-order, coalesced)
#pragma unroll
        for (int i = 0; i < 2; i++) {
            int idx = tid + i * 256;
            int k = idx >> 5, n4 = (idx & 31) * 4;
            float4 v = *(const float4*)(W + (size_t)(kt + k) * N + bn + n4);
            *(uint4*)&sB[k * 132 + n4] =
                make_uint4(f2tf(v.x), f2tf(v.y), f2tf(v.z), f2tf(v.w));
        }
        __syncthreads();

#pragma unroll
        for (int ks = 0; ks < 2; ks++) {
            uint32_t af[4][4], bf[4][2];
#pragma unroll
            for (int mf = 0; mf < 4; mf++) {
                int r = wm * 64 + mf * 16 + g, c = ks * 8 + t;
                af[mf][0] = sA[r * 20 + c];
                af[mf][1] = sA[(r + 8) * 20 + c];
                af[mf][2] = sA[r * 20 + c + 4];
                af[mf][3] = sA[(r + 8) * 20 + c + 4];
            }
#pragma unroll
            for (int nf = 0; nf < 4; nf++) {
                int kk = ks * 8 + t, n = wn * 32 + nf * 8 + g;
                bf[nf][0] = sB[kk * 132 + n];
                bf[nf][1] = sB[(kk + 4) * 132 + n];
            }
#pragma unroll
            for (int mf = 0; mf < 4; mf++)
#pragma unroll
                for (int nf = 0; nf < 4; nf++)
                    mma8(acc[mf][nf], af[mf], bf[nf]);
        }
        __syncthreads();
    }

    // Epilogue
#pragma unroll
    for (int mf = 0; mf < 4; mf++) {
#pragma unroll
        for (int half = 0; half < 2; half++) {
            const int r  = bm + wm * 64 + mf * 16 + g + half * 8;
            const int bq = r >> 11, tq = r & (TT - 1);
#pragma unroll
            for (int nf = 0; nf < 4; nf++) {
                const float v0 = acc[mf][nf][half * 2];
                const float v1 = acc[mf][nf][half * 2 + 1];
                const int col = bn + wn * 32 + nf * 8 + 2 * t;
                if (MODE == 0) {
                    float2 o = {v0, v1};
                    *(float2*)(C + (size_t)r * N + col) = o;
                } else if (MODE == 1) {
                    const int h = col >> 6, d = col & 63;
                    const float c  = cosb[tq * HD + d];
                    const float sn = sinb[tq * HD + d];
                    float* dst = &g_q[(((size_t)(bq * HQ + h) * TT + tq) << 6) + d];
                    dst[0] = v0 * c - v1 * sn;
                    dst[1] = v1 * c + v0 * sn;
                } else {
                    const int hk = col >> 7, pair = (col >> 6) & 1, d = col & 63;
                    if (pair == 0) {
                        const float c  = cosb[tq * HD + d];
                        const float sn = sinb[tq * HD + d];
                        float* dst = &g_k[(((size_t)(bq * HKV + hk) * TT + tq) << 6) + d];
                        dst[0] = v0 * c - v1 * sn;
                        dst[1] = v1 * c + v0 * sn;
                    } else {
                        float* dst = &g_vt[((size_t)(bq * HKV + hk) * HD + d) * TT + tq];
                        dst[0]  = v0;
                        dst[TT] = v1;   // row d+1
                    }
                }
            }
        }
    }
}

// ---------------------------------------------------------------------------
// Flash attention on mma.sync tf32. Block = 128 thr (4 warps), 64 q-rows/CTA,
// warp w owns rows 16w..16w+15. K-tile 64 keys. grid (BB*HQ, TT/64).
// ---------------------------------------------------------------------------
__global__ __launch_bounds__(128)
void attn_mma()
{
    __shared__ __align__(16) uint32_t sK[64 * 68];
    __shared__ __align__(16) uint32_t sV[64 * 68];   // transposed V: [d][key]
    __shared__ __align__(16) uint32_t sP[64 * 68];   // Q staging, then P

    const int tid = threadIdx.x, lane = tid & 31, g = lane >> 2, t = lane & 3;
    const int w   = tid >> 5;
    const int bh  = blockIdx.x, b = bh >> 4, h = bh & 15, hk = h >> 2;
    const int qt  = blockIdx.y * 64;
    const float SC = 0.1803368801111204f;  // 0.125 * log2(e)

    // stage Q (scaled, tf32)
    const float* Qb = g_q + (((size_t)bh * TT + qt) << 6);
#pragma unroll
    for (int i = 0; i < 8; i++) {
        int idx = tid + i * 128;
        int r = idx >> 4, c4 = (idx & 15) * 4;
        float4 v = *(const float4*)(Qb + r * 64 + c4);
        *(uint4*)&sP[r * 68 + c4] = make_uint4(
            f2tf(v.x * SC), f2tf(v.y * SC), f2tf(v.z * SC), f2tf(v.w * SC));
    }
    __syncthreads();

    uint32_t qf[8][4];
#pragma unroll
    for (int ks = 0; ks < 8; ks++) {
        int r = w * 16 + g, c = ks * 8 + t;
        qf[ks][0] = sP[r * 68 + c];
        qf[ks][1] = sP[(r + 8) * 68 + c];
        qf[ks][2] = sP[r * 68 + c + 4];
        qf[ks][3] = sP[(r + 8) * 68 + c + 4];
    }

    float o[8][4] = {};
    float m0 = -3.0e38f, m1 = -3.0e38f, l0 = 0.f, l1 = 0.f;

    const float* Kb = g_k  + (((size_t)(b * HKV + hk) * TT) << 6);
    const float* Vb = g_vt + ((size_t)(b * HKV + hk) * HD) * TT;

    for (int kt = 0; kt < TT; kt += 64) {
        // load K tile [key][d] and Vt tile [d][key]
#pragma unroll
        for (int i = 0; i < 8; i++) {
            int idx = tid + i * 128;
            int r = idx >> 4, c4 = (idx & 15) * 4;
            float4 kv = *(const float4*)(Kb + (size_t)(kt + r) * 64 + c4);
            *(uint4*)&sK[r * 68 + c4] =
                make_uint4(f2tf(kv.x), f2tf(kv.y), f2tf(kv.z), f2tf(kv.w));
            float4 vv = *(const float4*)(Vb + (size_t)r * TT + kt + c4);
            *(uint4*)&sV[r * 68 + c4] =
                make_uint4(f2tf(vv.x), f2tf(vv.y), f2tf(vv.z), f2tf(vv.w));
        }
        __syncthreads();

        // S = Q @ K^T (scaled, log2 domain)
        float s[8][4] = {};
#pragma unroll
        for (int ks = 0; ks < 8; ks++) {
#pragma unroll
            for (int nf = 0; nf < 8; nf++) {
                uint32_t bf[2];
                bf[0] = sK[(nf * 8 + g) * 68 + ks * 8 + t];
                bf[1] = sK[(nf * 8 + g) * 68 + ks * 8 + t + 4];
                mma8(s[nf], qf[ks], bf);
            }
        }

        // online softmax
        float tm0 = -3.0e38f, tm1 = -3.0e38f;
#pragma unroll
        for (int nf = 0; nf < 8; nf++) {
            tm0 = fmaxf(tm0, fmaxf(s[nf][0], s[nf][1]));
            tm1 = fmaxf(tm1, fmaxf(s[nf][2], s[nf][3]));
        }
        tm0 = fmaxf(tm0, __shfl_xor_sync(0xffffffffu, tm0, 1));
        tm0 = fmaxf(tm0, __shfl_xor_sync(0xffffffffu, tm0, 2));
        tm1 = fmaxf(tm1, __shfl_xor_sync(0xffffffffu, tm1, 1));
        tm1 = fmaxf(tm1, __shfl_xor_sync(0xffffffffu, tm1, 2));

        const float nm0 = fmaxf(m0, tm0), nm1 = fmaxf(m1, tm1);
        const float c0 = ex2(m0 - nm0), c1 = ex2(m1 - nm1);
        m0 = nm0; m1 = nm1;

        float lp0 = 0.f, lp1 = 0.f;
#pragma unroll
        for (int nf = 0; nf < 8; nf++) {
            float p0 = ex2(s[nf][0] - nm0);
            float p1 = ex2(s[nf][1] - nm0);
            float p2 = ex2(s[nf][2] - nm1);
            float p3 = ex2(s[nf][3] - nm1);
            lp0 += p0 + p1; lp1 += p2 + p3;
            int r = w * 16 + g, col = nf * 8 + 2 * t;
            *(uint2*)&sP[r * 68 + col]       = make_uint2(f2tf(p0), f2tf(p1));
            *(uint2*)&sP[(r + 8) * 68 + col] = make_uint2(f2tf(p2), f2tf(p3));
        }
        lp0 += __shfl_xor_sync(0xffffffffu, lp0, 1);
        lp0 += __shfl_xor_sync(0xffffffffu, lp0, 2);
        lp1 += __shfl_xor_sync(0xffffffffu, lp1, 1);
        lp1 += __shfl_xor_sync(0xffffffffu, lp1, 2);
        l0 = l0 * c0 + lp0;
        l1 = l1 * c1 + lp1;

#pragma unroll
        for (int nf = 0; nf < 8; nf++) {
            o[nf][0] *= c0; o[nf][1] *= c0;
            o[nf][2] *= c1; o[nf][3] *= c1;
        }
        __syncwarp();

        // O += P @ V
#pragma unroll
        for (int ks = 0; ks < 8; ks++) {
            uint32_t af[4];
            int r = w * 16 + g, c = ks * 8 + t;
            af[0] = sP[r * 68 + c];
            af[1] = sP[(r + 8) * 68 + c];
            af[2] = sP[r * 68 + c + 4];
            af[3] = sP[(r + 8) * 68 + c + 4];
#pragma unroll
            for (int nf = 0; nf < 8; nf++) {
                uint32_t bf[2];
                bf[0] = sV[(nf * 8 + g) * 68 + ks * 8 + t];
                bf[1] = sV[(nf * 8 + g) * 68 + ks * 8 + t + 4];
                mma8(o[nf], af, bf);
            }
        }
        __syncthreads();
    }

    const float i0 = 1.f / l0, i1 = 1.f / l1;
    const int tr = qt + w * 16 + g;
#pragma unroll
    for (int nf = 0; nf < 8; nf++) {
        int d = nf * 8 + 2 * t;
        float2 oa = {o[nf][0] * i0, o[nf][1] * i0};
        float2 ob = {o[nf][2] * i1, o[nf][3] * i1};
        *(float2*)(g_ao + ((size_t)(b * TT + tr)     * DM) + h * 64 + d) = oa;
        *(float2*)(g_ao + ((size_t)(b * TT + tr + 8) * DM) + h * 64 + d) = ob;
    }
}

// ---------------------------------------------------------------------------
extern "C" void kernel_launch(void* const* d_in, const int* in_sizes, int n_in,
                              void* d_out, int out_size)
{
    const float* x    = (const float*)d_in[0];
    const float* cosb = (const float*)d_in[1];
    const float* sinb = (const float*)d_in[2];
    const float* Wq   = (const float*)d_in[3];
    const float* Wkv  = (const float*)d_in[4];
    const float* Wo   = (const float*)d_in[5];
    float* out = (float*)d_out;

    void* p_ao = nullptr;
    cudaGetSymbolAddress(&p_ao, g_ao);

    {   // Q projection + RoPE
        dim3 grid(DM / 128, MROWS / 128);
        tcmm<1><<<grid, 256>>>(x, Wq, nullptr, DM, DM, cosb, sinb);
    }
    {   // KV projection + split (K RoPE, V transpose)
        dim3 grid((2 * HKV * HD) / 128, MROWS / 128);
        tcmm<2><<<grid, 256>>>(x, Wkv, nullptr, 2 * HKV * HD, DM, cosb, sinb);
    }
    {   // attention
        dim3 grid(BB * HQ, TT / 64);
        attn_mma<<<grid, 128>>>();
    }
    {   // output projection
        dim3 grid(DM / 128, MROWS / 128);
        tcmm<0><<<grid, 256>>>((const float*)p_ao, Wo, out, DM, DM,
                               nullptr, nullptr);
    }
}

// round 4
// speedup vs baseline: 3.7454x; 1.0109x over previous
#include <cuda_runtime.h>
#include <cstdint>

#define BB    4
#define TT    2048
#define DM    1024
#define HQ    16
#define HKV   4
#define HD    64
#define MROWS (BB*TT)

// Scratch (device globals). g_q/g_k/g_vt hold tf32-pre-rounded values.
__device__ float g_q [BB*HQ *TT*HD];    // (b*HQ+h, t, d)  pre-scaled by SC
__device__ float g_k [BB*HKV*TT*HD];    // (b*HKV+hk, t, d)
__device__ float g_vt[BB*HKV*HD*TT];    // (b*HKV+hk, d, t)
__device__ float g_ao[BB*TT*DM];        // (b, t, h*64+d)

#define SCQ 0.1803368801111204f         // 0.125 * log2(e)

// ---------------------------------------------------------------------------
__device__ __forceinline__ uint32_t f2tf(float f) {
    uint32_t r; asm("cvt.rna.tf32.f32 %0, %1;" : "=r"(r) : "f"(f)); return r;
}
__device__ __forceinline__ float ex2(float x) {
    float r; asm("ex2.approx.f32 %0, %1;" : "=f"(r) : "f"(x)); return r;
}
__device__ __forceinline__ uint32_t smem_u32(const void* p) {
    return (uint32_t)__cvta_generic_to_shared(p);
}
__device__ __forceinline__ void cpa16(uint32_t dst, const void* src) {
    asm volatile("cp.async.cg.shared.global [%0], [%1], 16;"
                 :: "r"(dst), "l"(src));
}
#define CP_COMMIT() asm volatile("cp.async.commit_group;" ::: "memory")
#define CP_WAIT1()  asm volatile("cp.async.wait_group 1;" ::: "memory")
#define CP_WAIT0()  asm volatile("cp.async.wait_group 0;" ::: "memory")

// D += A(m16 k8, tf32) * B(k8 n8, tf32)
__device__ __forceinline__ void mma8(float* d, const uint32_t* a, const uint32_t* b) {
    asm volatile(
        "mma.sync.aligned.m16n8k8.row.col.f32.tf32.tf32.f32 "
        "{%0,%1,%2,%3}, {%4,%5,%6,%7}, {%8,%9}, {%0,%1,%2,%3};"
        : "+f"(d[0]), "+f"(d[1]), "+f"(d[2]), "+f"(d[3])
        : "r"(a[0]), "r"(a[1]), "r"(a[2]), "r"(a[3]), "r"(b[0]), "r"(b[1]));
}

// ---------------------------------------------------------------------------
// tf32 mma GEMM, 128x128 tile, BK=16, 256 thr, 2(M)x4(N) warps, 64x32/warp.
// 2-stage register-staged smem pipeline (1 syncthreads per K-step).
// MODE: 0 plain store, 1 Q+RoPE(+SCQ)->g_q, 2 KV split (K RoPE->g_k, V->g_vt).
// All rounded to tf32 at store for MODE 1/2.
// ---------------------------------------------------------------------------
template <int MODE>
__global__ __launch_bounds__(256)
void tcmm(const float* __restrict__ A, const float* __restrict__ W,
          float* __restrict__ C, int N, int K,
          const float* __restrict__ cosb, const float* __restrict__ sinb)
{
    __shared__ __align__(16) uint32_t sA[2][128 * 20];   // [m][k], stride 20
    __shared__ __align__(16) uint32_t sB[2][16 * 132];   // [k][n], stride 132

    const int tid  = threadIdx.x;
    const int lane = tid & 31, g = lane >> 2, t = lane & 3;
    const int wid  = tid >> 5, wm = wid >> 2, wn = wid & 3;
    const int bm   = blockIdx.y * 128, bn = blockIdx.x * 128;

    float4 avS[2], bvS[2];

    auto ldg_tile = [&](int kt) {
#pragma unroll
        for (int i = 0; i < 2; i++) {
            int idx = tid + i * 256;
            avS[i] = *(const float4*)(A + (size_t)(bm + (idx >> 2)) * K +
                                      kt + (idx & 3) * 4);
            bvS[i] = *(const float4*)(W + (size_t)(kt + (idx >> 5)) * N +
                                      bn + (idx & 31) * 4);
        }
    };
    auto sts_tile = [&](int st) {
#pragma unroll
        for (int i = 0; i < 2; i++) {
            int idx = tid + i * 256;
            *(uint4*)&sA[st][(idx >> 2) * 20 + (idx & 3) * 4] = make_uint4(
                f2tf(avS[i].x), f2tf(avS[i].y), f2tf(avS[i].z), f2tf(avS[i].w));
            *(uint4*)&sB[st][(idx >> 5) * 132 + (idx & 31) * 4] = make_uint4(
                f2tf(bvS[i].x), f2tf(bvS[i].y), f2tf(bvS[i].z), f2tf(bvS[i].w));
        }
    };

    float acc[4][4][4] = {};

    ldg_tile(0);
    sts_tile(0);
    __syncthreads();

    const int NIT = K / 16;
    for (int it = 0; it < NIT; it++) {
        const int cur = it & 1;
        if (it + 1 < NIT) ldg_tile((it + 1) * 16);

#pragma unroll
        for (int ks = 0; ks < 2; ks++) {
            uint32_t af[4][4], bf[4][2];
#pragma unroll
            for (int mf = 0; mf < 4; mf++) {
                int r = wm * 64 + mf * 16 + g, c = ks * 8 + t;
                af[mf][0] = sA[cur][r * 20 + c];
                af[mf][1] = sA[cur][(r + 8) * 20 + c];
                af[mf][2] = sA[cur][r * 20 + c + 4];
                af[mf][3] = sA[cur][(r + 8) * 20 + c + 4];
            }
#pragma unroll
            for (int nf = 0; nf < 4; nf++) {
                int kk = ks * 8 + t, n = wn * 32 + nf * 8 + g;
                bf[nf][0] = sB[cur][kk * 132 + n];
                bf[nf][1] = sB[cur][(kk + 4) * 132 + n];
            }
#pragma unroll
            for (int mf = 0; mf < 4; mf++)
#pragma unroll
                for (int nf = 0; nf < 4; nf++)
                    mma8(acc[mf][nf], af[mf], bf[nf]);
        }
        if (it + 1 < NIT) sts_tile(cur ^ 1);
        __syncthreads();
    }

    // Epilogue
#pragma unroll
    for (int mf = 0; mf < 4; mf++) {
#pragma unroll
        for (int half = 0; half < 2; half++) {
            const int r  = bm + wm * 64 + mf * 16 + g + half * 8;
            const int bq = r >> 11, tq = r & (TT - 1);
#pragma unroll
            for (int nf = 0; nf < 4; nf++) {
                const float v0 = acc[mf][nf][half * 2];
                const float v1 = acc[mf][nf][half * 2 + 1];
                const int col = bn + wn * 32 + nf * 8 + 2 * t;
                if (MODE == 0) {
                    float2 o = {v0, v1};
                    *(float2*)(C + (size_t)r * N + col) = o;
                } else if (MODE == 1) {
                    const int h = col >> 6, d = col & 63;
                    const float c  = cosb[tq * HD + d];
                    const float sn = sinb[tq * HD + d];
                    float* dst = &g_q[(((size_t)(bq * HQ + h) * TT + tq) << 6) + d];
                    dst[0] = __uint_as_float(f2tf((v0 * c - v1 * sn) * SCQ));
                    dst[1] = __uint_as_float(f2tf((v1 * c + v0 * sn) * SCQ));
                } else {
                    const int hk = col >> 7, pair = (col >> 6) & 1, d = col & 63;
                    if (pair == 0) {
                        const float c  = cosb[tq * HD + d];
                        const float sn = sinb[tq * HD + d];
                        float* dst = &g_k[(((size_t)(bq * HKV + hk) * TT + tq) << 6) + d];
                        dst[0] = __uint_as_float(f2tf(v0 * c - v1 * sn));
                        dst[1] = __uint_as_float(f2tf(v1 * c + v0 * sn));
                    } else {
                        float* dst = &g_vt[((size_t)(bq * HKV + hk) * HD + d) * TT + tq];
                        dst[0]  = __uint_as_float(f2tf(v0));
                        dst[TT] = __uint_as_float(f2tf(v1));
                    }
                }
            }
        }
    }
}

// ---------------------------------------------------------------------------
// Flash attention, mma.sync tf32. 256 thr (8 warps), 128 q-rows/CTA (16/warp),
// K-tile 64, double-buffered cp.async K/V. grid (BB*HQ, TT/128).
// All operands pre-rounded to tf32 -> no cvt in the loop.
// ---------------------------------------------------------------------------
#define AST 68
#define TW  (64 * AST)     // words per K or V tile buffer
#define ATTN_SMEM ((4 * TW + 128 * AST) * 4)

__global__ __launch_bounds__(256)
void attn_mma()
{
    extern __shared__ __align__(16) uint32_t dsm[];
    uint32_t* sK = dsm;               // 2 stages
    uint32_t* sV = dsm + 2 * TW;      // 2 stages
    uint32_t* sP = dsm + 4 * TW;      // 128 x 68

    const int tid = threadIdx.x, lane = tid & 31, g = lane >> 2, t = lane & 3;
    const int w   = tid >> 5;
    const int bh  = blockIdx.x, b = bh >> 4, h = bh & 15, hk = h >> 2;
    const int qt  = blockIdx.y * 128;

    const float* Qb = g_q  + (((size_t)bh * TT + qt) << 6);
    const float* Kb = g_k  + (((size_t)(b * HKV + hk) * TT) << 6);
    const float* Vb = g_vt + ((size_t)(b * HKV + hk) * HD) * TT;

    // Q fragments direct from gmem (pre-scaled, pre-rounded)
    uint32_t qf[8][4];
    const int r0 = w * 16 + g;
#pragma unroll
    for (int ks = 0; ks < 8; ks++) {
        qf[ks][0] = __float_as_uint(Qb[(size_t)r0 * 64 + ks * 8 + t]);
        qf[ks][1] = __float_as_uint(Qb[(size_t)(r0 + 8) * 64 + ks * 8 + t]);
        qf[ks][2] = __float_as_uint(Qb[(size_t)r0 * 64 + ks * 8 + t + 4]);
        qf[ks][3] = __float_as_uint(Qb[(size_t)(r0 + 8) * 64 + ks * 8 + t + 4]);
    }

    const uint32_t smK = smem_u32(sK), smV = smem_u32(sV);

    auto load_tile = [&](int kt, int st) {
        const uint32_t kb = smK + st * TW * 4, vb = smV + st * TW * 4;
#pragma unroll
        for (int i = 0; i < 4; i++) {
            int idx = tid + i * 256;
            int rr = idx >> 4, c4 = (idx & 15) * 4;
            cpa16(kb + (rr * AST + c4) * 4, Kb + (size_t)(kt + rr) * 64 + c4);
            cpa16(vb + (rr * AST + c4) * 4, Vb + (size_t)rr * TT + kt + c4);
        }
    };

    float o[8][4] = {};
    float m0 = -3.0e38f, m1 = -3.0e38f, l0 = 0.f, l1 = 0.f;

    load_tile(0, 0);
    CP_COMMIT();

    const int NIT = TT / 64;
    for (int it = 0; it < NIT; it++) {
        const int cur = it & 1;
        if (it + 1 < NIT) { load_tile((it + 1) * 64, cur ^ 1); CP_COMMIT(); CP_WAIT1(); }
        else              { CP_WAIT0(); }
        __syncthreads();

        const uint32_t* sKc = sK + cur * TW;
        const uint32_t* sVc = sV + cur * TW;

        // S = Q @ K^T (log2 domain; scale folded into Q)
        float s[8][4] = {};
#pragma unroll
        for (int ks = 0; ks < 8; ks++)
#pragma unroll
            for (int nf = 0; nf < 8; nf++) {
                uint32_t bf[2];
                bf[0] = sKc[(nf * 8 + g) * AST + ks * 8 + t];
                bf[1] = sKc[(nf * 8 + g) * AST + ks * 8 + t + 4];
                mma8(s[nf], qf[ks], bf);
            }

        // online softmax
        float tm0 = -3.0e38f, tm1 = -3.0e38f;
#pragma unroll
        for (int nf = 0; nf < 8; nf++) {
            tm0 = fmaxf(tm0, fmaxf(s[nf][0], s[nf][1]));
            tm1 = fmaxf(tm1, fmaxf(s[nf][2], s[nf][3]));
        }
        tm0 = fmaxf(tm0, __shfl_xor_sync(0xffffffffu, tm0, 1));
        tm0 = fmaxf(tm0, __shfl_xor_sync(0xffffffffu, tm0, 2));
        tm1 = fmaxf(tm1, __shfl_xor_sync(0xffffffffu, tm1, 1));
        tm1 = fmaxf(tm1, __shfl_xor_sync(0xffffffffu, tm1, 2));

        const float nm0 = fmaxf(m0, tm0), nm1 = fmaxf(m1, tm1);
        const float c0 = ex2(m0 - nm0), c1 = ex2(m1 - nm1);
        m0 = nm0; m1 = nm1;

        float lp0 = 0.f, lp1 = 0.f;
#pragma unroll
        for (int nf = 0; nf < 8; nf++) {
            float p0 = ex2(s[nf][0] - nm0);
            float p1 = ex2(s[nf][1] - nm0);
            float p2 = ex2(s[nf][2] - nm1);
            float p3 = ex2(s[nf][3] - nm1);
            lp0 += p0 + p1; lp1 += p2 + p3;
            const int col = nf * 8 + 2 * t;
            *(uint2*)&sP[r0 * AST + col]       = make_uint2(f2tf(p0), f2tf(p1));
            *(uint2*)&sP[(r0 + 8) * AST + col] = make_uint2(f2tf(p2), f2tf(p3));
        }
        lp0 += __shfl_xor_sync(0xffffffffu, lp0, 1);
        lp0 += __shfl_xor_sync(0xffffffffu, lp0, 2);
        lp1 += __shfl_xor_sync(0xffffffffu, lp1, 1);
        lp1 += __shfl_xor_sync(0xffffffffu, lp1, 2);
        l0 = l0 * c0 + lp0;
        l1 = l1 * c1 + lp1;

#pragma unroll
        for (int nf = 0; nf < 8; nf++) {
            o[nf][0] *= c0; o[nf][1] *= c0;
            o[nf][2] *= c1; o[nf][3] *= c1;
        }
        __syncwarp();

        // O += P @ V  (P region is warp-private)
#pragma unroll
        for (int ks = 0; ks < 8; ks++) {
            uint32_t af[4];
            const int c = ks * 8 + t;
            af[0] = sP[r0 * AST + c];
            af[1] = sP[(r0 + 8) * AST + c];
            af[2] = sP[r0 * AST + c + 4];
            af[3] = sP[(r0 + 8) * AST + c + 4];
#pragma unroll
            for (int nf = 0; nf < 8; nf++) {
                uint32_t bf[2];
                bf[0] = sVc[(nf * 8 + g) * AST + ks * 8 + t];
                bf[1] = sVc[(nf * 8 + g) * AST + ks * 8 + t + 4];
                mma8(o[nf], af, bf);
            }
        }
        __syncthreads();
    }

    const float i0 = 1.f / l0, i1 = 1.f / l1;
    const int tr = qt + r0;
#pragma unroll
    for (int nf = 0; nf < 8; nf++) {
        const int d = nf * 8 + 2 * t;
        float2 oa = {o[nf][0] * i0, o[nf][1] * i0};
        float2 ob = {o[nf][2] * i1, o[nf][3] * i1};
        *(float2*)(g_ao + ((size_t)(b * TT + tr)     * DM) + h * 64 + d) = oa;
        *(float2*)(g_ao + ((size_t)(b * TT + tr + 8) * DM) + h * 64 + d) = ob;
    }
}

// ---------------------------------------------------------------------------
extern "C" void kernel_launch(void* const* d_in, const int* in_sizes, int n_in,
                              void* d_out, int out_size)
{
    const float* x    = (const float*)d_in[0];
    const float* cosb = (const float*)d_in[1];
    const float* sinb = (const float*)d_in[2];
    const float* Wq   = (const float*)d_in[3];
    const float* Wkv  = (const float*)d_in[4];
    const float* Wo   = (const float*)d_in[5];
    float* out = (float*)d_out;

    void* p_ao = nullptr;
    cudaGetSymbolAddress(&p_ao, g_ao);

    static bool attr_set = false;
    if (!attr_set) {
        cudaFuncSetAttribute(attn_mma, cudaFuncAttributeMaxDynamicSharedMemorySize,
                             ATTN_SMEM);
        attr_set = true;
    }

    {   // Q projection + RoPE (+softmax scale, tf32 round)
        dim3 grid(DM / 128, MROWS / 128);
        tcmm<1><<<grid, 256>>>(x, Wq, nullptr, DM, DM, cosb, sinb);
    }
    {   // KV projection + split (K RoPE, V transpose; tf32 round)
        dim3 grid((2 * HKV * HD) / 128, MROWS / 128);
        tcmm<2><<<grid, 256>>>(x, Wkv, nullptr, 2 * HKV * HD, DM, cosb, sinb);
    }
    {   // attention
        dim3 grid(BB * HQ, TT / 128);
        attn_mma<<<grid, 256, ATTN_SMEM>>>();
    }
    {   // output projection
        dim3 grid(DM / 128, MROWS / 128);
        tcmm<0><<<grid, 256>>>((const float*)p_ao, Wo, out, DM, DM,
                               nullptr, nullptr);
    }
}

// round 5
// speedup vs baseline: 7.4012x; 1.9761x over previous
#include <cuda_runtime.h>
#include <cuda_fp16.h>
#include <cstdint>

#define BB    4
#define TT    2048
#define DM    1024
#define HQ    16
#define HKV   4
#define HD    64
#define MROWS (BB*TT)

#define SCQ 0.1803368801111204f         // 0.125 * log2(e)

// fp16 scratch (device globals)
__device__ __half g_xh  [MROWS*DM];         // x, fp16
__device__ __half g_wqt [DM*DM];            // Wq^T  [n][k]
__device__ __half g_wkvt[(2*HKV*HD)*DM];    // Wkv^T [n][k]
__device__ __half g_wot [DM*DM];            // Wo^T  [n][k]
__device__ __half g_qh  [BB*HQ *TT*HD];     // (b*HQ+h, t, d), pre-scaled SCQ
__device__ __half g_kh  [BB*HKV*TT*HD];     // (b*HKV+hk, t, d)
__device__ __half g_vth [BB*HKV*HD*TT];     // (b*HKV+hk, d, t)
__device__ __half g_aoh [BB*TT*DM];         // (b, t, h*64+d)

// ---------------------------------------------------------------------------
__device__ __forceinline__ float ex2(float x) {
    float r; asm("ex2.approx.f32 %0, %1;" : "=f"(r) : "f"(x)); return r;
}
__device__ __forceinline__ uint32_t smem_u32(const void* p) {
    return (uint32_t)__cvta_generic_to_shared(p);
}
__device__ __forceinline__ void cpa16(uint32_t dst, const void* src) {
    asm volatile("cp.async.cg.shared.global [%0], [%1], 16;"
                 :: "r"(dst), "l"(src));
}
#define CP_COMMIT() asm volatile("cp.async.commit_group;" ::: "memory")
#define CP_WAIT1()  asm volatile("cp.async.wait_group 1;" ::: "memory")
#define CP_WAIT0()  asm volatile("cp.async.wait_group 0;" ::: "memory")

// D += A(m16 k16 f16) * B(k16 n8 f16), f32 accum
__device__ __forceinline__ void mma16(float* d, const uint32_t* a, const uint32_t* b) {
    asm volatile(
        "mma.sync.aligned.m16n8k16.row.col.f32.f16.f16.f32 "
        "{%0,%1,%2,%3}, {%4,%5,%6,%7}, {%8,%9}, {%0,%1,%2,%3};"
        : "+f"(d[0]), "+f"(d[1]), "+f"(d[2]), "+f"(d[3])
        : "r"(a[0]), "r"(a[1]), "r"(a[2]), "r"(a[3]), "r"(b[0]), "r"(b[1]));
}
__device__ __forceinline__ uint32_t packh2(float a, float b) {
    __half2 h = __floats2half2_rn(a, b);
    return *(uint32_t*)&h;
}

// ---------------------------------------------------------------------------
// Prep: fp32 -> fp16 copy (vectorized)
// ---------------------------------------------------------------------------
__global__ __launch_bounds__(256)
void cvt_fp16(const float* __restrict__ src, __half* __restrict__ dst, int n)
{
    int i = (blockIdx.x * 256 + threadIdx.x) * 4;
    if (i < n) {
        float4 v = *(const float4*)(src + i);
        uint2 o = {packh2(v.x, v.y), packh2(v.z, v.w)};
        *(uint2*)(dst + i) = o;
    }
}

// Prep: W[k][n] fp32 -> Wt[n][k] fp16. grid(N/32, K/32), block(32,8).
__global__ __launch_bounds__(256)
void trW(const float* __restrict__ W, __half* __restrict__ Wt, int Kd, int N)
{
    __shared__ float tile[32][33];
    const int k0 = blockIdx.y * 32, n0 = blockIdx.x * 32;
#pragma unroll
    for (int i = threadIdx.y; i < 32; i += 8)
        tile[i][threadIdx.x] = W[(size_t)(k0 + i) * N + n0 + threadIdx.x];
    __syncthreads();
#pragma unroll
    for (int i = threadIdx.y; i < 32; i += 8)
        Wt[(size_t)(n0 + i) * Kd + k0 + threadIdx.x] =
            __float2half(tile[threadIdx.x][i]);
}

// ---------------------------------------------------------------------------
// fp16 mma GEMM: C[M,N] = A[M,K] @ W[K,N], A fp16 [m][k], Wt fp16 [n][k].
// 128x128 tile, BK=32, 256 thr, 2(M)x4(N) warps, 64x32/warp.
// 2-stage cp.async pipeline. MODE: 0 fp32 store, 1 Q+RoPE(+SCQ)->g_qh,
// 2 KV split (K RoPE->g_kh, V->g_vth).
// ---------------------------------------------------------------------------
#define GST 20                       // words (=half2) per smem row
template <int MODE>
__global__ __launch_bounds__(256, 2)
void tcmm(const __half* __restrict__ A, const __half* __restrict__ Wt,
          float* __restrict__ C, int N, int K,
          const float* __restrict__ cosb, const float* __restrict__ sinb)
{
    __shared__ __align__(16) uint32_t sA[2][128 * GST];
    __shared__ __align__(16) uint32_t sB[2][128 * GST];

    const int tid  = threadIdx.x;
    const int lane = tid & 31, g = lane >> 2, t = lane & 3;
    const int wid  = tid >> 5, wm = wid >> 2, wn = wid & 3;
    const int bm   = blockIdx.y * 128, bn = blockIdx.x * 128;

    const uint32_t smA = smem_u32(sA), smB = smem_u32(sB);

    auto load_tile = [&](int kt, int st) {
        const uint32_t ab = smA + st * 128 * GST * 4;
        const uint32_t bb = smB + st * 128 * GST * 4;
#pragma unroll
        for (int i = 0; i < 2; i++) {
            int c = tid + i * 256;               // 0..511
            int rr = c >> 2, off = c & 3;        // row, 16B chunk
            cpa16(ab + rr * (GST * 4) + off * 16,
                  A + (size_t)(bm + rr) * K + kt + off * 8);
            cpa16(bb + rr * (GST * 4) + off * 16,
                  Wt + (size_t)(bn + rr) * K + kt + off * 8);
        }
    };

    float acc[4][4][4] = {};

    load_tile(0, 0);
    CP_COMMIT();

    const int NIT = K / 32;
    for (int it = 0; it < NIT; it++) {
        const int cur = it & 1;
        if (it + 1 < NIT) { load_tile((it + 1) * 32, cur ^ 1); CP_COMMIT(); CP_WAIT1(); }
        else              { CP_WAIT0(); }
        __syncthreads();

        const uint32_t* sAc = sA[cur];
        const uint32_t* sBc = sB[cur];
#pragma unroll
        for (int ks = 0; ks < 2; ks++) {
            uint32_t af[4][4], bf[4][2];
#pragma unroll
            for (int mf = 0; mf < 4; mf++) {
                const int r = wm * 64 + mf * 16 + g, c = ks * 8 + t;
                af[mf][0] = sAc[r * GST + c];
                af[mf][1] = sAc[(r + 8) * GST + c];
                af[mf][2] = sAc[r * GST + c + 4];
                af[mf][3] = sAc[(r + 8) * GST + c + 4];
            }
#pragma unroll
            for (int nf = 0; nf < 4; nf++) {
                const int n = wn * 32 + nf * 8 + g, c = ks * 8 + t;
                bf[nf][0] = sBc[n * GST + c];
                bf[nf][1] = sBc[n * GST + c + 4];
            }
#pragma unroll
            for (int mf = 0; mf < 4; mf++)
#pragma unroll
                for (int nf = 0; nf < 4; nf++)
                    mma16(acc[mf][nf], af[mf], bf[nf]);
        }
        __syncthreads();
    }

    // Epilogue
#pragma unroll
    for (int mf = 0; mf < 4; mf++) {
#pragma unroll
        for (int half = 0; half < 2; half++) {
            const int r  = bm + wm * 64 + mf * 16 + g + half * 8;
            const int bq = r >> 11, tq = r & (TT - 1);
#pragma unroll
            for (int nf = 0; nf < 4; nf++) {
                const float v0 = acc[mf][nf][half * 2];
                const float v1 = acc[mf][nf][half * 2 + 1];
                const int col = bn + wn * 32 + nf * 8 + 2 * t;
                if (MODE == 0) {
                    float2 o = {v0, v1};
                    *(float2*)(C + (size_t)r * N + col) = o;
                } else if (MODE == 1) {
                    const int h = col >> 6, d = col & 63;
                    const float c  = cosb[tq * HD + d];
                    const float sn = sinb[tq * HD + d];
                    uint32_t p = packh2((v0 * c - v1 * sn) * SCQ,
                                        (v1 * c + v0 * sn) * SCQ);
                    *(uint32_t*)&g_qh[(((size_t)(bq * HQ + h) * TT + tq) << 6) + d] = p;
                } else {
                    const int hk = col >> 7, pair = (col >> 6) & 1, d = col & 63;
                    if (pair == 0) {
                        const float c  = cosb[tq * HD + d];
                        const float sn = sinb[tq * HD + d];
                        uint32_t p = packh2(v0 * c - v1 * sn, v1 * c + v0 * sn);
                        *(uint32_t*)&g_kh[(((size_t)(bq * HKV + hk) * TT + tq) << 6) + d] = p;
                    } else {
                        __half* dst = &g_vth[((size_t)(bq * HKV + hk) * HD + d) * TT + tq];
                        dst[0]  = __float2half(v0);
                        dst[TT] = __float2half(v1);
                    }
                }
            }
        }
    }
}

// ---------------------------------------------------------------------------
// Flash attention, fp16 mma. 256 thr (8 warps), 128 q-rows/CTA, K-tile 64,
// double-buffered cp.async K/V. grid (BB*HQ, TT/128).
// ---------------------------------------------------------------------------
#define AST 36                        // words (=half2) per smem row
#define KTW (64 * AST)                // words per K/V tile stage
#define ATTN_SMEM ((4 * KTW + 128 * AST) * 4)

__global__ __launch_bounds__(256, 2)
void attn_mma()
{
    extern __shared__ __align__(16) uint32_t dsm[];
    uint32_t* sK = dsm;               // 2 stages
    uint32_t* sV = dsm + 2 * KTW;     // 2 stages
    uint32_t* sP = dsm + 4 * KTW;     // 128 x AST

    const int tid = threadIdx.x, lane = tid & 31, g = lane >> 2, t = lane & 3;
    const int w   = tid >> 5;
    const int bh  = blockIdx.x, b = bh >> 4, h = bh & 15, hk = h >> 2;
    const int qt  = blockIdx.y * 128;
    const int r0  = w * 16 + g;

    const __half* Qb = g_qh  + (((size_t)bh * TT + qt) << 6);
    const __half* Kb = g_kh  + (((size_t)(b * HKV + hk) * TT) << 6);
    const __half* Vb = g_vth + ((size_t)(b * HKV + hk) * HD) * TT;

    // Q fragments direct from gmem (pre-scaled, fp16 pairs)
    uint32_t qf[4][4];
#pragma unroll
    for (int ks = 0; ks < 4; ks++) {
        qf[ks][0] = *(const uint32_t*)(Qb + (size_t)r0 * 64 + (ks * 8 + t) * 2);
        qf[ks][1] = *(const uint32_t*)(Qb + (size_t)(r0 + 8) * 64 + (ks * 8 + t) * 2);
        qf[ks][2] = *(const uint32_t*)(Qb + (size_t)r0 * 64 + (ks * 8 + t + 4) * 2);
        qf[ks][3] = *(const uint32_t*)(Qb + (size_t)(r0 + 8) * 64 + (ks * 8 + t + 4) * 2);
    }

    const uint32_t smK = smem_u32(sK), smV = smem_u32(sV);

    auto load_tile = [&](int kt, int st) {
        const uint32_t kb = smK + st * KTW * 4, vb = smV + st * KTW * 4;
#pragma unroll
        for (int i = 0; i < 2; i++) {
            int c = tid + i * 256;               // 0..511
            int rr = c >> 3, off = c & 7;        // row, 16B chunk (8 halves)
            cpa16(kb + rr * (AST * 4) + off * 16,
                  Kb + (size_t)(kt + rr) * 64 + off * 8);
            cpa16(vb + rr * (AST * 4) + off * 16,
                  Vb + (size_t)rr * TT + kt + off * 8);
        }
    };

    float o[8][4] = {};
    float m0 = -3.0e38f, m1 = -3.0e38f, l0 = 0.f, l1 = 0.f;

    load_tile(0, 0);
    CP_COMMIT();

    const int NIT = TT / 64;
    for (int it = 0; it < NIT; it++) {
        const int cur = it & 1;
        if (it + 1 < NIT) { load_tile((it + 1) * 64, cur ^ 1); CP_COMMIT(); CP_WAIT1(); }
        else              { CP_WAIT0(); }
        __syncthreads();

        const uint32_t* sKc = sK + cur * KTW;
        const uint32_t* sVc = sV + cur * KTW;

        // S = Q @ K^T (log2 domain; scale folded into Q)
        float s[8][4] = {};
#pragma unroll
        for (int ks = 0; ks < 4; ks++)
#pragma unroll
            for (int nf = 0; nf < 8; nf++) {
                uint32_t bf[2];
                bf[0] = sKc[(nf * 8 + g) * AST + ks * 8 + t];
                bf[1] = sKc[(nf * 8 + g) * AST + ks * 8 + t + 4];
                mma16(s[nf], qf[ks], bf);
            }

        // online softmax
        float tm0 = -3.0e38f, tm1 = -3.0e38f;
#pragma unroll
        for (int nf = 0; nf < 8; nf++) {
            tm0 = fmaxf(tm0, fmaxf(s[nf][0], s[nf][1]));
            tm1 = fmaxf(tm1, fmaxf(s[nf][2], s[nf][3]));
        }
        tm0 = fmaxf(tm0, __shfl_xor_sync(0xffffffffu, tm0, 1));
        tm0 = fmaxf(tm0, __shfl_xor_sync(0xffffffffu, tm0, 2));
        tm1 = fmaxf(tm1, __shfl_xor_sync(0xffffffffu, tm1, 1));
        tm1 = fmaxf(tm1, __shfl_xor_sync(0xffffffffu, tm1, 2));

        const float nm0 = fmaxf(m0, tm0), nm1 = fmaxf(m1, tm1);
        const float c0 = ex2(m0 - nm0), c1 = ex2(m1 - nm1);
        m0 = nm0; m1 = nm1;

        float lp0 = 0.f, lp1 = 0.f;
#pragma unroll
        for (int nf = 0; nf < 8; nf++) {
            float p0 = ex2(s[nf][0] - nm0);
            float p1 = ex2(s[nf][1] - nm0);
            float p2 = ex2(s[nf][2] - nm1);
            float p3 = ex2(s[nf][3] - nm1);
            lp0 += p0 + p1; lp1 += p2 + p3;
            sP[r0 * AST + nf * 4 + t]       = packh2(p0, p1);
            sP[(r0 + 8) * AST + nf * 4 + t] = packh2(p2, p3);
        }
        lp0 += __shfl_xor_sync(0xffffffffu, lp0, 1);
        lp0 += __shfl_xor_sync(0xffffffffu, lp0, 2);
        lp1 += __shfl_xor_sync(0xffffffffu, lp1, 1);
        lp1 += __shfl_xor_sync(0xffffffffu, lp1, 2);
        l0 = l0 * c0 + lp0;
        l1 = l1 * c1 + lp1;

#pragma unroll
        for (int nf = 0; nf < 8; nf++) {
            o[nf][0] *= c0; o[nf][1] *= c0;
            o[nf][2] *= c1; o[nf][3] *= c1;
        }
        __syncwarp();

        // O += P @ V  (P rows are warp-private)
#pragma unroll
        for (int ks = 0; ks < 4; ks++) {
            uint32_t af[4];
            af[0] = sP[r0 * AST + ks * 8 + t];
            af[1] = sP[(r0 + 8) * AST + ks * 8 + t];
            af[2] = sP[r0 * AST + ks * 8 + t + 4];
            af[3] = sP[(r0 + 8) * AST + ks * 8 + t + 4];
#pragma unroll
            for (int nf = 0; nf < 8; nf++) {
                uint32_t bf[2];
                bf[0] = sVc[(nf * 8 + g) * AST + ks * 8 + t];
                bf[1] = sVc[(nf * 8 + g) * AST + ks * 8 + t + 4];
                mma16(o[nf], af, bf);
            }
        }
        __syncthreads();
    }

    const float i0 = 1.f / l0, i1 = 1.f / l1;
    const int tr = qt + r0;
#pragma unroll
    for (int nf = 0; nf < 8; nf++) {
        const int d = nf * 8 + 2 * t;
        *(uint32_t*)&g_aoh[((size_t)(b * TT + tr)     * DM) + h * 64 + d] =
            packh2(o[nf][0] * i0, o[nf][1] * i0);
        *(uint32_t*)&g_aoh[((size_t)(b * TT + tr + 8) * DM) + h * 64 + d] =
            packh2(o[nf][2] * i1, o[nf][3] * i1);
    }
}

// ---------------------------------------------------------------------------
extern "C" void kernel_launch(void* const* d_in, const int* in_sizes, int n_in,
                              void* d_out, int out_size)
{
    const float* x    = (const float*)d_in[0];
    const float* cosb = (const float*)d_in[1];
    const float* sinb = (const float*)d_in[2];
    const float* Wq   = (const float*)d_in[3];
    const float* Wkv  = (const float*)d_in[4];
    const float* Wo   = (const float*)d_in[5];
    float* out = (float*)d_out;

    __half *p_xh = nullptr, *p_wqt = nullptr, *p_wkvt = nullptr,
           *p_wot = nullptr, *p_aoh = nullptr;
    cudaGetSymbolAddress((void**)&p_xh,  g_xh);
    cudaGetSymbolAddress((void**)&p_wqt, g_wqt);
    cudaGetSymbolAddress((void**)&p_wkvt,g_wkvt);
    cudaGetSymbolAddress((void**)&p_wot, g_wot);
    cudaGetSymbolAddress((void**)&p_aoh, g_aoh);

    cudaFuncSetAttribute(attn_mma, cudaFuncAttributeMaxDynamicSharedMemorySize,
                         ATTN_SMEM);

    // Prep: x -> fp16; W -> transposed fp16
    cvt_fp16<<<(MROWS * DM) / (256 * 4), 256>>>(x, p_xh, MROWS * DM);
    { dim3 g(DM / 32, DM / 32), blk(32, 8);  trW<<<g, blk>>>(Wq,  p_wqt,  DM, DM); }
    { dim3 g((2*HKV*HD)/32, DM/32), blk(32, 8); trW<<<g, blk>>>(Wkv, p_wkvt, DM, 2*HKV*HD); }
    { dim3 g(DM / 32, DM / 32), blk(32, 8);  trW<<<g, blk>>>(Wo,  p_wot,  DM, DM); }

    {   // Q projection + RoPE (+softmax scale)
        dim3 grid(DM / 128, MROWS / 128);
        tcmm<1><<<grid, 256>>>(p_xh, p_wqt, nullptr, DM, DM, cosb, sinb);
    }
    {   // KV projection + split (K RoPE, V transpose)
        dim3 grid((2 * HKV * HD) / 128, MROWS / 128);
        tcmm<2><<<grid, 256>>>(p_xh, p_wkvt, nullptr, 2 * HKV * HD, DM, cosb, sinb);
    }
    {   // attention
        dim3 grid(BB * HQ, TT / 128);
        attn_mma<<<grid, 256, ATTN_SMEM>>>();
    }
    {   // output projection
        dim3 grid(DM / 128, MROWS / 128);
        tcmm<0><<<grid, 256>>>(p_aoh, p_wot, out, DM, DM, nullptr, nullptr);
    }
}

// round 6
// speedup vs baseline: 8.0513x; 1.0878x over previous
#include <cuda_runtime.h>
#include <cuda_fp16.h>
#include <cstdint>

#define BB    4
#define TT    2048
#define DM    1024
#define HQ    16
#define HKV   4
#define HD    64
#define MROWS (BB*TT)

#define SCQ 0.1803368801111204f         // 0.125 * log2(e)

// fp16 scratch (device globals)
__device__ __half g_xh  [MROWS*DM];         // x, fp16
__device__ __half g_wqt [DM*DM];            // Wq^T  [n][k]
__device__ __half g_wkvt[(2*HKV*HD)*DM];    // Wkv^T [n][k]
__device__ __half g_wot [DM*DM];            // Wo^T  [n][k]
__device__ __half g_qh  [BB*HQ *TT*HD];     // (b*HQ+h, t, d), pre-scaled SCQ
__device__ __half g_kh  [BB*HKV*TT*HD];     // (b*HKV+hk, t, d)
__device__ __half g_vth [BB*HKV*HD*TT];     // (b*HKV+hk, d, t)
__device__ __half g_aoh [BB*TT*DM];         // (b, t, h*64+d)

// ---------------------------------------------------------------------------
__device__ __forceinline__ float ex2(float x) {
    float r; asm("ex2.approx.f32 %0, %1;" : "=f"(r) : "f"(x)); return r;
}
__device__ __forceinline__ uint32_t smem_u32(const void* p) {
    return (uint32_t)__cvta_generic_to_shared(p);
}
__device__ __forceinline__ void cpa16(uint32_t dst, const void* src) {
    asm volatile("cp.async.cg.shared.global [%0], [%1], 16;"
                 :: "r"(dst), "l"(src));
}
#define CP_COMMIT() asm volatile("cp.async.commit_group;" ::: "memory")
#define CP_WAIT1()  asm volatile("cp.async.wait_group 1;" ::: "memory")
#define CP_WAIT0()  asm volatile("cp.async.wait_group 0;" ::: "memory")

// 4x m8n8 b16 matrices in one shot; per-lane row address in 'addr'.
__device__ __forceinline__ void ldm4(uint32_t* r, uint32_t addr) {
    asm volatile("ldmatrix.sync.aligned.m8n8.x4.shared.b16 {%0,%1,%2,%3}, [%4];"
                 : "=r"(r[0]), "=r"(r[1]), "=r"(r[2]), "=r"(r[3]) : "r"(addr));
}

// D += A(m16 k16 f16) * B(k16 n8 f16), f32 accum
__device__ __forceinline__ void mma16(float* d, const uint32_t* a, const uint32_t* b) {
    asm volatile(
        "mma.sync.aligned.m16n8k16.row.col.f32.f16.f16.f32 "
        "{%0,%1,%2,%3}, {%4,%5,%6,%7}, {%8,%9}, {%0,%1,%2,%3};"
        : "+f"(d[0]), "+f"(d[1]), "+f"(d[2]), "+f"(d[3])
        : "r"(a[0]), "r"(a[1]), "r"(a[2]), "r"(a[3]), "r"(b[0]), "r"(b[1]));
}
__device__ __forceinline__ uint32_t packh2(float a, float b) {
    __half2 h = __floats2half2_rn(a, b);
    return *(uint32_t*)&h;
}

// ---------------------------------------------------------------------------
// Prep kernels
// ---------------------------------------------------------------------------
__global__ __launch_bounds__(256)
void cvt_fp16(const float* __restrict__ src, __half* __restrict__ dst, int n)
{
    int i = (blockIdx.x * 256 + threadIdx.x) * 4;
    if (i < n) {
        float4 v = *(const float4*)(src + i);
        uint2 o = {packh2(v.x, v.y), packh2(v.z, v.w)};
        *(uint2*)(dst + i) = o;
    }
}

// W[k][n] fp32 -> Wt[n][k] fp16. grid(N/32, K/32), block(32,8).
__global__ __launch_bounds__(256)
void trW(const float* __restrict__ W, __half* __restrict__ Wt, int Kd, int N)
{
    __shared__ float tile[32][33];
    const int k0 = blockIdx.y * 32, n0 = blockIdx.x * 32;
#pragma unroll
    for (int i = threadIdx.y; i < 32; i += 8)
        tile[i][threadIdx.x] = W[(size_t)(k0 + i) * N + n0 + threadIdx.x];
    __syncthreads();
#pragma unroll
    for (int i = threadIdx.y; i < 32; i += 8)
        Wt[(size_t)(n0 + i) * Kd + k0 + threadIdx.x] =
            __float2half(tile[threadIdx.x][i]);
}

// ---------------------------------------------------------------------------
// fp16 mma GEMM: C[M,N] = A[M,K] @ W[K,N], A fp16 [m][k], Wt fp16 [n][k].
// 128x128 tile, BK=32, 256 thr, 2(M)x4(N) warps, 64x32/warp, ldmatrix frags.
// ---------------------------------------------------------------------------
#define GST 20                       // 32-bit words per smem row
template <int MODE>
__global__ __launch_bounds__(256, 2)
void tcmm(const __half* __restrict__ A, const __half* __restrict__ Wt,
          float* __restrict__ C, int N, int K,
          const float* __restrict__ cosb, const float* __restrict__ sinb)
{
    __shared__ __align__(16) uint32_t sA[2][128 * GST];
    __shared__ __align__(16) uint32_t sB[2][128 * GST];

    const int tid  = threadIdx.x;
    const int lane = tid & 31, g = lane >> 2, t = lane & 3;
    const int wid  = tid >> 5, wm = wid >> 2, wn = wid & 3;
    const int bm   = blockIdx.y * 128, bn = blockIdx.x * 128;

    // ldmatrix per-lane row/col selectors
    const int rselA = (lane & 7) + ((lane >> 3) & 1) * 8;
    const int cselA = ((lane >> 4) & 1) * 16;
    const int rselB = (lane & 7) + ((lane >> 4) & 1) * 8;
    const int cselB = ((lane >> 3) & 1) * 16;

    const uint32_t smA = smem_u32(sA), smB = smem_u32(sB);

    auto load_tile = [&](int kt, int st) {
        const uint32_t ab = smA + st * 128 * GST * 4;
        const uint32_t bb = smB + st * 128 * GST * 4;
#pragma unroll
        for (int i = 0; i < 2; i++) {
            int c = tid + i * 256;
            int rr = c >> 2, off = c & 3;
            cpa16(ab + rr * (GST * 4) + off * 16,
                  A + (size_t)(bm + rr) * K + kt + off * 8);
            cpa16(bb + rr * (GST * 4) + off * 16,
                  Wt + (size_t)(bn + rr) * K + kt + off * 8);
        }
    };

    float acc[4][4][4] = {};

    load_tile(0, 0);
    CP_COMMIT();

    const int NIT = K / 32;
    for (int it = 0; it < NIT; it++) {
        const int cur = it & 1;
        if (it + 1 < NIT) { load_tile((it + 1) * 32, cur ^ 1); CP_COMMIT(); CP_WAIT1(); }
        else              { CP_WAIT0(); }
        __syncthreads();

        const uint32_t smAc = smA + cur * 128 * GST * 4;
        const uint32_t smBc = smB + cur * 128 * GST * 4;
#pragma unroll
        for (int ks = 0; ks < 2; ks++) {
            uint32_t af[4][4];
#pragma unroll
            for (int mf = 0; mf < 4; mf++)
                ldm4(af[mf], smAc + (wm * 64 + mf * 16 + rselA) * (GST * 4)
                               + cselA + ks * 32);
#pragma unroll
            for (int nfp = 0; nfp < 4; nfp += 2) {
                uint32_t bf[4];
                ldm4(bf, smBc + (wn * 32 + nfp * 8 + rselB) * (GST * 4)
                           + cselB + ks * 32);
#pragma unroll
                for (int mf = 0; mf < 4; mf++) {
                    mma16(acc[mf][nfp],     af[mf], bf);
                    mma16(acc[mf][nfp + 1], af[mf], bf + 2);
                }
            }
        }
        __syncthreads();
    }

    // Epilogue
#pragma unroll
    for (int mf = 0; mf < 4; mf++) {
#pragma unroll
        for (int half = 0; half < 2; half++) {
            const int r  = bm + wm * 64 + mf * 16 + g + half * 8;
            const int bq = r >> 11, tq = r & (TT - 1);
#pragma unroll
            for (int nf = 0; nf < 4; nf++) {
                const float v0 = acc[mf][nf][half * 2];
                const float v1 = acc[mf][nf][half * 2 + 1];
                const int col = bn + wn * 32 + nf * 8 + 2 * t;
                if (MODE == 0) {
                    float2 o = {v0, v1};
                    *(float2*)(C + (size_t)r * N + col) = o;
                } else if (MODE == 1) {
                    const int h = col >> 6, d = col & 63;
                    const float c  = cosb[tq * HD + d];
                    const float sn = sinb[tq * HD + d];
                    uint32_t p = packh2((v0 * c - v1 * sn) * SCQ,
                                        (v1 * c + v0 * sn) * SCQ);
                    *(uint32_t*)&g_qh[(((size_t)(bq * HQ + h) * TT + tq) << 6) + d] = p;
                } else {
                    const int hk = col >> 7, pair = (col >> 6) & 1, d = col & 63;
                    if (pair == 0) {
                        const float c  = cosb[tq * HD + d];
                        const float sn = sinb[tq * HD + d];
                        uint32_t p = packh2(v0 * c - v1 * sn, v1 * c + v0 * sn);
                        *(uint32_t*)&g_kh[(((size_t)(bq * HKV + hk) * TT + tq) << 6) + d] = p;
                    } else {
                        __half* dst = &g_vth[((size_t)(bq * HKV + hk) * HD + d) * TT + tq];
                        dst[0]  = __float2half(v0);
                        dst[TT] = __float2half(v1);
                    }
                }
            }
        }
    }
}

// ---------------------------------------------------------------------------
// Flash attention, fp16 mma + ldmatrix. 256 thr, 128 q-rows/CTA, K-tile 64,
// double-buffered cp.async K/V. grid (BB*HQ, TT/128).
// ---------------------------------------------------------------------------
#define AST 36                        // 32-bit words per smem row
#define KTW (64 * AST)                // words per K/V tile stage
#define ATTN_SMEM ((4 * KTW + 128 * AST) * 4)

__global__ __launch_bounds__(256, 2)
void attn_mma()
{
    extern __shared__ __align__(16) uint32_t dsm[];
    uint32_t* sK = dsm;               // 2 stages
    uint32_t* sV = dsm + 2 * KTW;     // 2 stages
    uint32_t* sP = dsm + 4 * KTW;     // 128 x AST

    const int tid = threadIdx.x, lane = tid & 31, g = lane >> 2, t = lane & 3;
    const int w   = tid >> 5;
    const int bh  = blockIdx.x, b = bh >> 4, h = bh & 15, hk = h >> 2;
    const int qt  = blockIdx.y * 128;
    const int r0  = w * 16 + g;

    const int rselA = (lane & 7) + ((lane >> 3) & 1) * 8;
    const int cselA = ((lane >> 4) & 1) * 16;
    const int rselB = (lane & 7) + ((lane >> 4) & 1) * 8;
    const int cselB = ((lane >> 3) & 1) * 16;

    const __half* Qb = g_qh  + (((size_t)bh * TT + qt) << 6);
    const __half* Kb = g_kh  + (((size_t)(b * HKV + hk) * TT) << 6);
    const __half* Vb = g_vth + ((size_t)(b * HKV + hk) * HD) * TT;

    // Q fragments direct from gmem (pre-scaled, fp16 pairs)
    uint32_t qf[4][4];
#pragma unroll
    for (int ks = 0; ks < 4; ks++) {
        qf[ks][0] = *(const uint32_t*)(Qb + (size_t)r0 * 64 + (ks * 8 + t) * 2);
        qf[ks][1] = *(const uint32_t*)(Qb + (size_t)(r0 + 8) * 64 + (ks * 8 + t) * 2);
        qf[ks][2] = *(const uint32_t*)(Qb + (size_t)r0 * 64 + (ks * 8 + t + 4) * 2);
        qf[ks][3] = *(const uint32_t*)(Qb + (size_t)(r0 + 8) * 64 + (ks * 8 + t + 4) * 2);
    }

    const uint32_t smK = smem_u32(sK), smV = smem_u32(sV), smP = smem_u32(sP);

    auto load_tile = [&](int kt, int st) {
        const uint32_t kb = smK + st * KTW * 4, vb = smV + st * KTW * 4;
#pragma unroll
        for (int i = 0; i < 2; i++) {
            int c = tid + i * 256;
            int rr = c >> 3, off = c & 7;
            cpa16(kb + rr * (AST * 4) + off * 16,
                  Kb + (size_t)(kt + rr) * 64 + off * 8);
            cpa16(vb + rr * (AST * 4) + off * 16,
                  Vb + (size_t)rr * TT + kt + off * 8);
        }
    };

    float o[8][4] = {};
    float m0 = -3.0e38f, m1 = -3.0e38f, l0 = 0.f, l1 = 0.f;

    load_tile(0, 0);
    CP_COMMIT();

    const int NIT = TT / 64;
    for (int it = 0; it < NIT; it++) {
        const int cur = it & 1;
        if (it + 1 < NIT) { load_tile((it + 1) * 64, cur ^ 1); CP_COMMIT(); CP_WAIT1(); }
        else              { CP_WAIT0(); }
        __syncthreads();

        const uint32_t smKc = smK + cur * KTW * 4;
        const uint32_t smVc = smV + cur * KTW * 4;

        // S = Q @ K^T (log2 domain; scale folded into Q)
        float s[8][4] = {};
#pragma unroll
        for (int nfp = 0; nfp < 8; nfp += 2) {
            const uint32_t ka = smKc + (nfp * 8 + rselB) * (AST * 4) + cselB;
#pragma unroll
            for (int ks = 0; ks < 4; ks++) {
                uint32_t bf[4];
                ldm4(bf, ka + ks * 32);
                mma16(s[nfp],     qf[ks], bf);
                mma16(s[nfp + 1], qf[ks], bf + 2);
            }
        }

        // online softmax
        float tm0 = -3.0e38f, tm1 = -3.0e38f;
#pragma unroll
        for (int nf = 0; nf < 8; nf++) {
            tm0 = fmaxf(tm0, fmaxf(s[nf][0], s[nf][1]));
            tm1 = fmaxf(tm1, fmaxf(s[nf][2], s[nf][3]));
        }
        tm0 = fmaxf(tm0, __shfl_xor_sync(0xffffffffu, tm0, 1));
        tm0 = fmaxf(tm0, __shfl_xor_sync(0xffffffffu, tm0, 2));
        tm1 = fmaxf(tm1, __shfl_xor_sync(0xffffffffu, tm1, 1));
        tm1 = fmaxf(tm1, __shfl_xor_sync(0xffffffffu, tm1, 2));

        const float nm0 = fmaxf(m0, tm0), nm1 = fmaxf(m1, tm1);
        const float c0 = ex2(m0 - nm0), c1 = ex2(m1 - nm1);
        m0 = nm0; m1 = nm1;

        float lp0 = 0.f, lp1 = 0.f;
#pragma unroll
        for (int nf = 0; nf < 8; nf++) {
            float p0 = ex2(s[nf][0] - nm0);
            float p1 = ex2(s[nf][1] - nm0);
            float p2 = ex2(s[nf][2] - nm1);
            float p3 = ex2(s[nf][3] - nm1);
            lp0 += p0 + p1; lp1 += p2 + p3;
            sP[r0 * AST + nf * 4 + t]       = packh2(p0, p1);
            sP[(r0 + 8) * AST + nf * 4 + t] = packh2(p2, p3);
        }
        lp0 += __shfl_xor_sync(0xffffffffu, lp0, 1);
        lp0 += __shfl_xor_sync(0xffffffffu, lp0, 2);
        lp1 += __shfl_xor_sync(0xffffffffu, lp1, 1);
        lp1 += __shfl_xor_sync(0xffffffffu, lp1, 2);
        l0 = l0 * c0 + lp0;
        l1 = l1 * c1 + lp1;

#pragma unroll
        for (int nf = 0; nf < 8; nf++) {
            o[nf][0] *= c0; o[nf][1] *= c0;
            o[nf][2] *= c1; o[nf][3] *= c1;
        }
        __syncwarp();

        // O += P @ V  (P rows are warp-private)
        uint32_t af[4][4];
        const uint32_t pa = smP + (w * 16 + rselA) * (AST * 4) + cselA;
#pragma unroll
        for (int ks = 0; ks < 4; ks++) ldm4(af[ks], pa + ks * 32);
#pragma unroll
        for (int nfp = 0; nfp < 8; nfp += 2) {
            const uint32_t va = smVc + (nfp * 8 + rselB) * (AST * 4) + cselB;
#pragma unroll
            for (int ks = 0; ks < 4; ks++) {
                uint32_t bf[4];
                ldm4(bf, va + ks * 32);
                mma16(o[nfp],     af[ks], bf);
                mma16(o[nfp + 1], af[ks], bf + 2);
            }
        }
        __syncthreads();
    }

    const float i0 = 1.f / l0, i1 = 1.f / l1;
    const int tr = qt + r0;
#pragma unroll
    for (int nf = 0; nf < 8; nf++) {
        const int d = nf * 8 + 2 * t;
        *(uint32_t*)&g_aoh[((size_t)(b * TT + tr)     * DM) + h * 64 + d] =
            packh2(o[nf][0] * i0, o[nf][1] * i0);
        *(uint32_t*)&g_aoh[((size_t)(b * TT + tr + 8) * DM) + h * 64 + d] =
            packh2(o[nf][2] * i1, o[nf][3] * i1);
    }
}

// ---------------------------------------------------------------------------
extern "C" void kernel_launch(void* const* d_in, const int* in_sizes, int n_in,
                              void* d_out, int out_size)
{
    const float* x    = (const float*)d_in[0];
    const float* cosb = (const float*)d_in[1];
    const float* sinb = (const float*)d_in[2];
    const float* Wq   = (const float*)d_in[3];
    const float* Wkv  = (const float*)d_in[4];
    const float* Wo   = (const float*)d_in[5];
    float* out = (float*)d_out;

    __half *p_xh = nullptr, *p_wqt = nullptr, *p_wkvt = nullptr,
           *p_wot = nullptr, *p_aoh = nullptr;
    cudaGetSymbolAddress((void**)&p_xh,  g_xh);
    cudaGetSymbolAddress((void**)&p_wqt, g_wqt);
    cudaGetSymbolAddress((void**)&p_wkvt,g_wkvt);
    cudaGetSymbolAddress((void**)&p_wot, g_wot);
    cudaGetSymbolAddress((void**)&p_aoh, g_aoh);

    cudaFuncSetAttribute(attn_mma, cudaFuncAttributeMaxDynamicSharedMemorySize,
                         ATTN_SMEM);

    // Prep: x -> fp16; W -> transposed fp16
    cvt_fp16<<<(MROWS * DM) / (256 * 4), 256>>>(x, p_xh, MROWS * DM);
    { dim3 g(DM / 32, DM / 32), blk(32, 8);  trW<<<g, blk>>>(Wq,  p_wqt,  DM, DM); }
    { dim3 g((2*HKV*HD)/32, DM/32), blk(32, 8); trW<<<g, blk>>>(Wkv, p_wkvt, DM, 2*HKV*HD); }
    { dim3 g(DM / 32, DM / 32), blk(32, 8);  trW<<<g, blk>>>(Wo,  p_wot,  DM, DM); }

    {   // Q projection + RoPE (+softmax scale)
        dim3 grid(DM / 128, MROWS / 128);
        tcmm<1><<<grid, 256>>>(p_xh, p_wqt, nullptr, DM, DM, cosb, sinb);
    }
    {   // KV projection + split (K RoPE, V transpose)
        dim3 grid((2 * HKV * HD) / 128, MROWS / 128);
        tcmm<2><<<grid, 256>>>(p_xh, p_wkvt, nullptr, 2 * HKV * HD, DM, cosb, sinb);
    }
    {   // attention
        dim3 grid(BB * HQ, TT / 128);
        attn_mma<<<grid, 256, ATTN_SMEM>>>();
    }
    {   // output projection
        dim3 grid(DM / 128, MROWS / 128);
        tcmm<0><<<grid, 256>>>(p_aoh, p_wot, out, DM, DM, nullptr, nullptr);
    }
}

// round 8
// speedup vs baseline: 8.7795x; 1.0904x over previous
#include <cuda_runtime.h>
#include <cuda_fp16.h>
#include <cstdint>

#define BB    4
#define TT    2048
#define DM    1024
#define HQ    16
#define HKV   4
#define HD    64
#define MROWS (BB*TT)

#define SCQ 0.1803368801111204f         // 0.125 * log2(e)

// fp16 scratch (device globals)
__device__ __half g_xh  [MROWS*DM];         // x, fp16
__device__ __half g_wqt [DM*DM];            // Wq^T  [n][k]
__device__ __half g_wkvt[(2*HKV*HD)*DM];    // Wkv^T [n][k]
__device__ __half g_wot [DM*DM];            // Wo^T  [n][k]
__device__ __half g_qh  [BB*HQ *TT*HD];     // (b*HQ+h, t, d), pre-scaled SCQ
__device__ __half g_kh  [BB*HKV*TT*HD];     // (b*HKV+hk, t, d)
__device__ __half g_vth [BB*HKV*HD*TT];     // (b*HKV+hk, d, t)
__device__ __half g_aoh [BB*TT*DM];         // (b, t, h*64+d)

// ---------------------------------------------------------------------------
__device__ __forceinline__ float ex2(float x) {
    float r; asm("ex2.approx.f32 %0, %1;" : "=f"(r) : "f"(x)); return r;
}
__device__ __forceinline__ uint32_t ex2h2(uint32_t x) {
    uint32_t r; asm("ex2.approx.f16x2 %0, %1;" : "=r"(r) : "r"(x)); return r;
}
__device__ __forceinline__ uint32_t smem_u32(const void* p) {
    return (uint32_t)__cvta_generic_to_shared(p);
}
__device__ __forceinline__ void cpa16(uint32_t dst, const void* src) {
    asm volatile("cp.async.cg.shared.global [%0], [%1], 16;"
                 :: "r"(dst), "l"(src));
}
#define CP_COMMIT() asm volatile("cp.async.commit_group;" ::: "memory")
#define CP_WAIT0()  asm volatile("cp.async.wait_group 0;" ::: "memory")

__device__ __forceinline__ void ldm4(uint32_t* r, uint32_t addr) {
    asm volatile("ldmatrix.sync.aligned.m8n8.x4.shared.b16 {%0,%1,%2,%3}, [%4];"
                 : "=r"(r[0]), "=r"(r[1]), "=r"(r[2]), "=r"(r[3]) : "r"(addr));
}
__device__ __forceinline__ void mma16(float* d, const uint32_t* a, const uint32_t* b) {
    asm volatile(
        "mma.sync.aligned.m16n8k16.row.col.f32.f16.f16.f32 "
        "{%0,%1,%2,%3}, {%4,%5,%6,%7}, {%8,%9}, {%0,%1,%2,%3};"
        : "+f"(d[0]), "+f"(d[1]), "+f"(d[2]), "+f"(d[3])
        : "r"(a[0]), "r"(a[1]), "r"(a[2]), "r"(a[3]), "r"(b[0]), "r"(b[1]));
}
__device__ __forceinline__ uint32_t packh2(float a, float b) {
    __half2 h = __floats2half2_rn(a, b);
    return *(uint32_t*)&h;
}

// ---------------------------------------------------------------------------
// Prep kernels
// ---------------------------------------------------------------------------
__global__ __launch_bounds__(256)
void cvt_fp16(const float* __restrict__ src, __half* __restrict__ dst, int n)
{
    int i = (blockIdx.x * 256 + threadIdx.x) * 4;
    if (i < n) {
        float4 v = *(const float4*)(src + i);
        uint2 o = {packh2(v.x, v.y), packh2(v.z, v.w)};
        *(uint2*)(dst + i) = o;
    }
}

__global__ __launch_bounds__(256)
void trW(const float* __restrict__ W, __half* __restrict__ Wt, int Kd, int N)
{
    __shared__ float tile[32][33];
    const int k0 = blockIdx.y * 32, n0 = blockIdx.x * 32;
#pragma unroll
    for (int i = threadIdx.y; i < 32; i += 8)
        tile[i][threadIdx.x] = W[(size_t)(k0 + i) * N + n0 + threadIdx.x];
    __syncthreads();
#pragma unroll
    for (int i = threadIdx.y; i < 32; i += 8)
        Wt[(size_t)(n0 + i) * Kd + k0 + threadIdx.x] =
            __float2half(tile[threadIdx.x][i]);
}

// ---------------------------------------------------------------------------
// fp16 mma GEMM: C[M,N] = A[M,K] @ W[K,N], A fp16 [m][k], Wt fp16 [n][k].
// 128x128 tile, BK=32, 256 thr, 2(M)x4(N) warps, ldmatrix.
// One barrier/iter: wait(tile it) -> sync -> load(it+1) -> compute(it).
// ---------------------------------------------------------------------------
#define GST 20
template <int MODE>
__global__ __launch_bounds__(256, 2)
void tcmm(const __half* __restrict__ A, const __half* __restrict__ Wt,
          float* __restrict__ C, int N, int K,
          const float* __restrict__ cosb, const float* __restrict__ sinb)
{
    __shared__ __align__(16) uint32_t sA[2][128 * GST];
    __shared__ __align__(16) uint32_t sB[2][128 * GST];

    const int tid  = threadIdx.x;
    const int lane = tid & 31, g = lane >> 2, t = lane & 3;
    const int wid  = tid >> 5, wm = wid >> 2, wn = wid & 3;
    const int bm   = blockIdx.y * 128, bn = blockIdx.x * 128;

    const int rselA = (lane & 7) + ((lane >> 3) & 1) * 8;
    const int cselA = ((lane >> 4) & 1) * 16;
    const int rselB = (lane & 7) + ((lane >> 4) & 1) * 8;
    const int cselB = ((lane >> 3) & 1) * 16;

    const uint32_t smA = smem_u32(sA), smB = smem_u32(sB);

    auto load_tile = [&](int kt, int st) {
        const uint32_t ab = smA + st * 128 * GST * 4;
        const uint32_t bb = smB + st * 128 * GST * 4;
#pragma unroll
        for (int i = 0; i < 2; i++) {
            int c = tid + i * 256;
            int rr = c >> 2, off = c & 3;
            cpa16(ab + rr * (GST * 4) + off * 16,
                  A + (size_t)(bm + rr) * K + kt + off * 8);
            cpa16(bb + rr * (GST * 4) + off * 16,
                  Wt + (size_t)(bn + rr) * K + kt + off * 8);
        }
    };

    float acc[4][4][4] = {};

    load_tile(0, 0);
    CP_COMMIT();

    const int NIT = K / 32;
    for (int it = 0; it < NIT; it++) {
        const int cur = it & 1;
        CP_WAIT0();                    // tile it arrived
        __syncthreads();               // everyone done reading buffer cur^1
        if (it + 1 < NIT) { load_tile((it + 1) * 32, cur ^ 1); CP_COMMIT(); }

        const uint32_t smAc = smA + cur * 128 * GST * 4;
        const uint32_t smBc = smB + cur * 128 * GST * 4;
#pragma unroll
        for (int ks = 0; ks < 2; ks++) {
            uint32_t af[4][4];
#pragma unroll
            for (int mf = 0; mf < 4; mf++)
                ldm4(af[mf], smAc + (wm * 64 + mf * 16 + rselA) * (GST * 4)
                               + cselA + ks * 32);
#pragma unroll
            for (int nfp = 0; nfp < 4; nfp += 2) {
                uint32_t bf[4];
                ldm4(bf, smBc + (wn * 32 + nfp * 8 + rselB) * (GST * 4)
                           + cselB + ks * 32);
#pragma unroll
                for (int mf = 0; mf < 4; mf++) {
                    mma16(acc[mf][nfp],     af[mf], bf);
                    mma16(acc[mf][nfp + 1], af[mf], bf + 2);
                }
            }
        }
    }

    // Epilogue
#pragma unroll
    for (int mf = 0; mf < 4; mf++) {
#pragma unroll
        for (int half = 0; half < 2; half++) {
            const int r  = bm + wm * 64 + mf * 16 + g + half * 8;
            const int bq = r >> 11, tq = r & (TT - 1);
#pragma unroll
            for (int nf = 0; nf < 4; nf++) {
                const float v0 = acc[mf][nf][half * 2];
                const float v1 = acc[mf][nf][half * 2 + 1];
                const int col = bn + wn * 32 + nf * 8 + 2 * t;
                if (MODE == 0) {
                    float2 o = {v0, v1};
                    *(float2*)(C + (size_t)r * N + col) = o;
                } else if (MODE == 1) {
                    const int h = col >> 6, d = col & 63;
                    const float c  = cosb[tq * HD + d];
                    const float sn = sinb[tq * HD + d];
                    uint32_t p = packh2((v0 * c - v1 * sn) * SCQ,
                                        (v1 * c + v0 * sn) * SCQ);
                    *(uint32_t*)&g_qh[(((size_t)(bq * HQ + h) * TT + tq) << 6) + d] = p;
                } else {
                    const int hk = col >> 7, pair = (col >> 6) & 1, d = col & 63;
                    if (pair == 0) {
                        const float c  = cosb[tq * HD + d];
                        const float sn = sinb[tq * HD + d];
                        uint32_t p = packh2(v0 * c - v1 * sn, v1 * c + v0 * sn);
                        *(uint32_t*)&g_kh[(((size_t)(bq * HKV + hk) * TT + tq) << 6) + d] = p;
                    } else {
                        __half* dst = &g_vth[((size_t)(bq * HKV + hk) * HD + d) * TT + tq];
                        dst[0]  = __float2half(v0);
                        dst[TT] = __float2half(v1);
                    }
                }
            }
        }
    }
}

// ---------------------------------------------------------------------------
// Flash attention: fp16 mma + ldmatrix, P entirely in registers,
// ex2.approx.f16x2 softmax, one barrier per K-tile (wait->sync->load->compute).
// 256 thr, 128 q-rows/CTA, K-tile 64. grid (BB*HQ, TT/128).
// ---------------------------------------------------------------------------
#define AST 36
#define KTW (64 * AST)
#define ATTN_SMEM ((4 * KTW) * 4)

__global__ __launch_bounds__(256, 2)
void attn_mma()
{
    extern __shared__ __align__(16) uint32_t dsm[];
    uint32_t* sK = dsm;               // 2 stages
    uint32_t* sV = dsm + 2 * KTW;     // 2 stages

    const int tid = threadIdx.x, lane = tid & 31, g = lane >> 2, t = lane & 3;
    const int w   = tid >> 5;
    const int bh  = blockIdx.x, b = bh >> 4, h = bh & 15, hk = h >> 2;
    const int qt  = blockIdx.y * 128;
    const int r0  = w * 16 + g;

    const int rselB = (lane & 7) + ((lane >> 4) & 1) * 8;
    const int cselB = ((lane >> 3) & 1) * 16;

    const __half* Qb = g_qh  + (((size_t)bh * TT + qt) << 6);
    const __half* Kb = g_kh  + (((size_t)(b * HKV + hk) * TT) << 6);
    const __half* Vb = g_vth + ((size_t)(b * HKV + hk) * HD) * TT;

    // Q fragments direct from gmem (pre-scaled, fp16 pairs)
    uint32_t qf[4][4];
#pragma unroll
    for (int ks = 0; ks < 4; ks++) {
        qf[ks][0] = *(const uint32_t*)(Qb + (size_t)r0 * 64 + (ks * 8 + t) * 2);
        qf[ks][1] = *(const uint32_t*)(Qb + (size_t)(r0 + 8) * 64 + (ks * 8 + t) * 2);
        qf[ks][2] = *(const uint32_t*)(Qb + (size_t)r0 * 64 + (ks * 8 + t + 4) * 2);
        qf[ks][3] = *(const uint32_t*)(Qb + (size_t)(r0 + 8) * 64 + (ks * 8 + t + 4) * 2);
    }

    const uint32_t smK = smem_u32(sK), smV = smem_u32(sV);

    auto load_tile = [&](int kt, int st) {
        const uint32_t kb = smK + st * KTW * 4, vb = smV + st * KTW * 4;
#pragma unroll
        for (int i = 0; i < 2; i++) {
            int c = tid + i * 256;
            int rr = c >> 3, off = c & 7;
            cpa16(kb + rr * (AST * 4) + off * 16,
                  Kb + (size_t)(kt + rr) * 64 + off * 8);
            cpa16(vb + rr * (AST * 4) + off * 16,
                  Vb + (size_t)rr * TT + kt + off * 8);
        }
    };

    float o[8][4] = {};
    float m0 = -3.0e38f, m1 = -3.0e38f, l0 = 0.f, l1 = 0.f;

    load_tile(0, 0);
    CP_COMMIT();

    const int NIT = TT / 64;
    for (int it = 0; it < NIT; it++) {
        const int cur = it & 1;
        CP_WAIT0();                    // tile it arrived
        __syncthreads();               // everyone done reading buffer cur^1
        if (it + 1 < NIT) { load_tile((it + 1) * 64, cur ^ 1); CP_COMMIT(); }

        const uint32_t smKc = smK + cur * KTW * 4;
        const uint32_t smVc = smV + cur * KTW * 4;

        // S = Q @ K^T (log2 domain; scale folded into Q)
        float s[8][4] = {};
#pragma unroll
        for (int nfp = 0; nfp < 8; nfp += 2) {
            const uint32_t ka = smKc + (nfp * 8 + rselB) * (AST * 4) + cselB;
#pragma unroll
            for (int ks = 0; ks < 4; ks++) {
                uint32_t bf[4];
                ldm4(bf, ka + ks * 32);
                mma16(s[nfp],     qf[ks], bf);
                mma16(s[nfp + 1], qf[ks], bf + 2);
            }
        }

        // online softmax (rows g -> m0/l0, rows g+8 -> m1/l1)
        float tm0 = -3.0e38f, tm1 = -3.0e38f;
#pragma unroll
        for (int nf = 0; nf < 8; nf++) {
            tm0 = fmaxf(tm0, fmaxf(s[nf][0], s[nf][1]));
            tm1 = fmaxf(tm1, fmaxf(s[nf][2], s[nf][3]));
        }
        tm0 = fmaxf(tm0, __shfl_xor_sync(0xffffffffu, tm0, 1));
        tm0 = fmaxf(tm0, __shfl_xor_sync(0xffffffffu, tm0, 2));
        tm1 = fmaxf(tm1, __shfl_xor_sync(0xffffffffu, tm1, 1));
        tm1 = fmaxf(tm1, __shfl_xor_sync(0xffffffffu, tm1, 2));

        const float nm0 = fmaxf(m0, tm0), nm1 = fmaxf(m1, tm1);
        const float c0 = ex2(m0 - nm0), c1 = ex2(m1 - nm1);
        m0 = nm0; m1 = nm1;

        // P fragments in registers: ex2 on packed half2; layout == A fragment
        uint32_t af[4][4];
        float lp0 = 0.f, lp1 = 0.f;
#pragma unroll
        for (int ks = 0; ks < 4; ks++) {
            const int lo = 2 * ks, hi = 2 * ks + 1;
            af[ks][0] = ex2h2(packh2(s[lo][0] - nm0, s[lo][1] - nm0));
            af[ks][1] = ex2h2(packh2(s[lo][2] - nm1, s[lo][3] - nm1));
            af[ks][2] = ex2h2(packh2(s[hi][0] - nm0, s[hi][1] - nm0));
            af[ks][3] = ex2h2(packh2(s[hi][2] - nm1, s[hi][3] - nm1));
            float2 f;
            f = __half22float2(*(__half2*)&af[ks][0]); lp0 += f.x + f.y;
            f = __half22float2(*(__half2*)&af[ks][2]); lp0 += f.x + f.y;
            f = __half22float2(*(__half2*)&af[ks][1]); lp1 += f.x + f.y;
            f = __half22float2(*(__half2*)&af[ks][3]); lp1 += f.x + f.y;
        }
        lp0 += __shfl_xor_sync(0xffffffffu, lp0, 1);
        lp0 += __shfl_xor_sync(0xffffffffu, lp0, 2);
        lp1 += __shfl_xor_sync(0xffffffffu, lp1, 1);
        lp1 += __shfl_xor_sync(0xffffffffu, lp1, 2);
        l0 = l0 * c0 + lp0;
        l1 = l1 * c1 + lp1;

#pragma unroll
        for (int nf = 0; nf < 8; nf++) {
            o[nf][0] *= c0; o[nf][1] *= c0;
            o[nf][2] *= c1; o[nf][3] *= c1;
        }

        // O += P @ V  (P straight from registers)
#pragma unroll
        for (int nfp = 0; nfp < 8; nfp += 2) {
            const uint32_t va = smVc + (nfp * 8 + rselB) * (AST * 4) + cselB;
#pragma unroll
            for (int ks = 0; ks < 4; ks++) {
                uint32_t bf[4];
                ldm4(bf, va + ks * 32);
                mma16(o[nfp],     af[ks], bf);
                mma16(o[nfp + 1], af[ks], bf + 2);
            }
        }
    }

    const float i0 = 1.f / l0, i1 = 1.f / l1;
    const int tr = qt + r0;
#pragma unroll
    for (int nf = 0; nf < 8; nf++) {
        const int d = nf * 8 + 2 * t;
        *(uint32_t*)&g_aoh[((size_t)(b * TT + tr)     * DM) + h * 64 + d] =
            packh2(o[nf][0] * i0, o[nf][1] * i0);
        *(uint32_t*)&g_aoh[((size_t)(b * TT + tr + 8) * DM) + h * 64 + d] =
            packh2(o[nf][2] * i1, o[nf][3] * i1);
    }
}

// ---------------------------------------------------------------------------
extern "C" void kernel_launch(void* const* d_in, const int* in_sizes, int n_in,
                              void* d_out, int out_size)
{
    const float* x    = (const float*)d_in[0];
    const float* cosb = (const float*)d_in[1];
    const float* sinb = (const float*)d_in[2];
    const float* Wq   = (const float*)d_in[3];
    const float* Wkv  = (const float*)d_in[4];
    const float* Wo   = (const float*)d_in[5];
    float* out = (float*)d_out;

    __half *p_xh = nullptr, *p_wqt = nullptr, *p_wkvt = nullptr,
           *p_wot = nullptr, *p_aoh = nullptr;
    cudaGetSymbolAddress((void**)&p_xh,  g_xh);
    cudaGetSymbolAddress((void**)&p_wqt, g_wqt);
    cudaGetSymbolAddress((void**)&p_wkvt,g_wkvt);
    cudaGetSymbolAddress((void**)&p_wot, g_wot);
    cudaGetSymbolAddress((void**)&p_aoh, g_aoh);

    cudaFuncSetAttribute(attn_mma, cudaFuncAttributeMaxDynamicSharedMemorySize,
                         ATTN_SMEM);

    // Prep: x -> fp16; W -> transposed fp16
    cvt_fp16<<<(MROWS * DM) / (256 * 4), 256>>>(x, p_xh, MROWS * DM);
    { dim3 g(DM / 32, DM / 32), blk(32, 8);  trW<<<g, blk>>>(Wq,  p_wqt,  DM, DM); }
    { dim3 g((2*HKV*HD)/32, DM/32), blk(32, 8); trW<<<g, blk>>>(Wkv, p_wkvt, DM, 2*HKV*HD); }
    { dim3 g(DM / 32, DM / 32), blk(32, 8);  trW<<<g, blk>>>(Wo,  p_wot,  DM, DM); }

    {   // Q projection + RoPE (+softmax scale)
        dim3 grid(DM / 128, MROWS / 128);
        tcmm<1><<<grid, 256>>>(p_xh, p_wqt, nullptr, DM, DM, cosb, sinb);
    }
    {   // KV projection + split (K RoPE, V transpose)
        dim3 grid((2 * HKV * HD) / 128, MROWS / 128);
        tcmm<2><<<grid, 256>>>(p_xh, p_wkvt, nullptr, 2 * HKV * HD, DM, cosb, sinb);
    }
    {   // attention
        dim3 grid(BB * HQ, TT / 128);
        attn_mma<<<grid, 256, ATTN_SMEM>>>();
    }
    {   // output projection
        dim3 grid(DM / 128, MROWS / 128);
        tcmm<0><<<grid, 256>>>(p_aoh, p_wot, out, DM, DM, nullptr, nullptr);
    }
}

// round 9
// speedup vs baseline: 9.1551x; 1.0428x over previous
#include <cuda_runtime.h>
#include <cuda_fp16.h>
#include <cstdint>

#define BB    4
#define TT    2048
#define DM    1024
#define HQ    16
#define HKV   4
#define HD    64
#define MROWS (BB*TT)

#define SCQ 0.1803368801111204f         // 0.125 * log2(e)

// fp16 scratch (device globals)
__device__ __half g_xh  [MROWS*DM];
__device__ __half g_wqt [DM*DM];            // Wq^T  [n][k]
__device__ __half g_wkvt[(2*HKV*HD)*DM];    // Wkv^T [n][k]
__device__ __half g_wot [DM*DM];            // Wo^T  [n][k]
__device__ __half g_qh  [BB*HQ *TT*HD];     // (b*HQ+h, t, d), pre-scaled SCQ
__device__ __half g_kh  [BB*HKV*TT*HD];     // (b*HKV+hk, t, d)
__device__ __half g_vth [BB*HKV*HD*TT];     // (b*HKV+hk, d, t)
__device__ __half g_aoh [BB*TT*DM];         // (b, t, h*64+d)

// ---------------------------------------------------------------------------
__device__ __forceinline__ float ex2(float x) {
    float r; asm("ex2.approx.f32 %0, %1;" : "=f"(r) : "f"(x)); return r;
}
__device__ __forceinline__ uint32_t ex2h2(uint32_t x) {
    uint32_t r; asm("ex2.approx.f16x2 %0, %1;" : "=r"(r) : "r"(x)); return r;
}
__device__ __forceinline__ uint32_t smem_u32(const void* p) {
    return (uint32_t)__cvta_generic_to_shared(p);
}
__device__ __forceinline__ void cpa16(uint32_t dst, const void* src) {
    asm volatile("cp.async.cg.shared.global [%0], [%1], 16;"
                 :: "r"(dst), "l"(src));
}
#define CP_COMMIT() asm volatile("cp.async.commit_group;" ::: "memory")
#define CP_WAIT0()  asm volatile("cp.async.wait_group 0;" ::: "memory")

__device__ __forceinline__ void ldm4(uint32_t* r, uint32_t addr) {
    asm volatile("ldmatrix.sync.aligned.m8n8.x4.shared.b16 {%0,%1,%2,%3}, [%4];"
                 : "=r"(r[0]), "=r"(r[1]), "=r"(r[2]), "=r"(r[3]) : "r"(addr));
}
__device__ __forceinline__ void mma16(float* d, const uint32_t* a, const uint32_t* b) {
    asm volatile(
        "mma.sync.aligned.m16n8k16.row.col.f32.f16.f16.f32 "
        "{%0,%1,%2,%3}, {%4,%5,%6,%7}, {%8,%9}, {%0,%1,%2,%3};"
        : "+f"(d[0]), "+f"(d[1]), "+f"(d[2]), "+f"(d[3])
        : "r"(a[0]), "r"(a[1]), "r"(a[2]), "r"(a[3]), "r"(b[0]), "r"(b[1]));
}
__device__ __forceinline__ uint32_t packh2(float a, float b) {
    __half2 h = __floats2half2_rn(a, b);
    return *(uint32_t*)&h;
}

// ---------------------------------------------------------------------------
// Prep kernels
// ---------------------------------------------------------------------------
__global__ __launch_bounds__(256)
void cvt_fp16(const float* __restrict__ src, __half* __restrict__ dst, int n)
{
    int i = (blockIdx.x * 256 + threadIdx.x) * 4;
    if (i < n) {
        float4 v = *(const float4*)(src + i);
        uint2 o = {packh2(v.x, v.y), packh2(v.z, v.w)};
        *(uint2*)(dst + i) = o;
    }
}

// All three W transposes in one launch. blockIdx.z: 0=Wq, 1=Wkv, 2=Wo.
__global__ __launch_bounds__(256)
void trW3(const float* __restrict__ Wq, const float* __restrict__ Wkv,
          const float* __restrict__ Wo,
          __half* __restrict__ wqt, __half* __restrict__ wkvt,
          __half* __restrict__ wot)
{
    const float* W; __half* Wt; int N;
    if (blockIdx.z == 0)      { W = Wq;  Wt = wqt;  N = DM; }
    else if (blockIdx.z == 1) { W = Wkv; Wt = wkvt; N = 2 * HKV * HD; }
    else                      { W = Wo;  Wt = wot;  N = DM; }
    const int n0 = blockIdx.x * 32;
    if (n0 >= N) return;
    const int k0 = blockIdx.y * 32;

    __shared__ float tile[32][33];
#pragma unroll
    for (int i = threadIdx.y; i < 32; i += 8)
        tile[i][threadIdx.x] = W[(size_t)(k0 + i) * N + n0 + threadIdx.x];
    __syncthreads();
#pragma unroll
    for (int i = threadIdx.y; i < 32; i += 8)
        Wt[(size_t)(n0 + i) * DM + k0 + threadIdx.x] =
            __float2half(tile[threadIdx.x][i]);
}

// ---------------------------------------------------------------------------
// fp16 mma GEMM: C[M,N] = A[M,K] @ W[K,N]. 128x128 tile, BK=64, 256 thr,
// 2(M)x4(N) warps, ldmatrix, dynamic smem, 1 barrier/iter.
// ---------------------------------------------------------------------------
#define GST 36                               // words per smem row (64h + pad)
#define GTW (128 * GST)                      // words per tile stage
#define GEMM_SMEM ((4 * GTW) * 4)            // 2 stages x (A,B)

template <int MODE>
__global__ __launch_bounds__(256, 2)
void tcmm(const __half* __restrict__ A, const __half* __restrict__ Wt,
          float* __restrict__ C, int N, int K,
          const float* __restrict__ cosb, const float* __restrict__ sinb)
{
    extern __shared__ __align__(16) uint32_t gsm[];
    // layout: [stage0 A][stage0 B][stage1 A][stage1 B]
    const int tid  = threadIdx.x;
    const int lane = tid & 31, g = lane >> 2, t = lane & 3;
    const int wid  = tid >> 5, wm = wid >> 2, wn = wid & 3;
    const int bm   = blockIdx.y * 128, bn = blockIdx.x * 128;

    const int rselA = (lane & 7) + ((lane >> 3) & 1) * 8;
    const int cselA = ((lane >> 4) & 1) * 16;
    const int rselB = (lane & 7) + ((lane >> 4) & 1) * 8;
    const int cselB = ((lane >> 3) & 1) * 16;

    const uint32_t smBase = smem_u32(gsm);

    auto load_tile = [&](int kt, int st) {
        const uint32_t ab = smBase + st * 2 * GTW * 4;
        const uint32_t bb = ab + GTW * 4;
#pragma unroll
        for (int i = 0; i < 4; i++) {
            int c = tid + i * 256;           // 0..1023
            int rr = c >> 3, off = c & 7;    // row, 16B chunk (8 halves)
            cpa16(ab + rr * (GST * 4) + off * 16,
                  A + (size_t)(bm + rr) * K + kt + off * 8);
            cpa16(bb + rr * (GST * 4) + off * 16,
                  Wt + (size_t)(bn + rr) * K + kt + off * 8);
        }
    };

    float acc[4][4][4] = {};

    load_tile(0, 0);
    CP_COMMIT();

    const int NIT = K / 64;
    for (int it = 0; it < NIT; it++) {
        const int cur = it & 1;
        CP_WAIT0();
        __syncthreads();
        if (it + 1 < NIT) { load_tile((it + 1) * 64, cur ^ 1); CP_COMMIT(); }

        const uint32_t smAc = smBase + cur * 2 * GTW * 4;
        const uint32_t smBc = smAc + GTW * 4;
#pragma unroll
        for (int ks = 0; ks < 4; ks++) {
            uint32_t af[4][4];
#pragma unroll
            for (int mf = 0; mf < 4; mf++)
                ldm4(af[mf], smAc + (wm * 64 + mf * 16 + rselA) * (GST * 4)
                               + cselA + ks * 32);
#pragma unroll
            for (int nfp = 0; nfp < 4; nfp += 2) {
                uint32_t bf[4];
                ldm4(bf, smBc + (wn * 32 + nfp * 8 + rselB) * (GST * 4)
                           + cselB + ks * 32);
#pragma unroll
                for (int mf = 0; mf < 4; mf++) {
                    mma16(acc[mf][nfp],     af[mf], bf);
                    mma16(acc[mf][nfp + 1], af[mf], bf + 2);
                }
            }
        }
    }

    // Epilogue
#pragma unroll
    for (int mf = 0; mf < 4; mf++) {
#pragma unroll
        for (int half = 0; half < 2; half++) {
            const int r  = bm + wm * 64 + mf * 16 + g + half * 8;
            const int bq = r >> 11, tq = r & (TT - 1);
#pragma unroll
            for (int nf = 0; nf < 4; nf++) {
                const float v0 = acc[mf][nf][half * 2];
                const float v1 = acc[mf][nf][half * 2 + 1];
                const int col = bn + wn * 32 + nf * 8 + 2 * t;
                if (MODE == 0) {
                    float2 o = {v0, v1};
                    *(float2*)(C + (size_t)r * N + col) = o;
                } else if (MODE == 1) {
                    const int h = col >> 6, d = col & 63;
                    const float c  = cosb[tq * HD + d];
                    const float sn = sinb[tq * HD + d];
                    uint32_t p = packh2((v0 * c - v1 * sn) * SCQ,
                                        (v1 * c + v0 * sn) * SCQ);
                    *(uint32_t*)&g_qh[(((size_t)(bq * HQ + h) * TT + tq) << 6) + d] = p;
                } else {
                    const int hk = col >> 7, pair = (col >> 6) & 1, d = col & 63;
                    if (pair == 0) {
                        const float c  = cosb[tq * HD + d];
                        const float sn = sinb[tq * HD + d];
                        uint32_t p = packh2(v0 * c - v1 * sn, v1 * c + v0 * sn);
                        *(uint32_t*)&g_kh[(((size_t)(bq * HKV + hk) * TT + tq) << 6) + d] = p;
                    } else {
                        __half* dst = &g_vth[((size_t)(bq * HKV + hk) * HD + d) * TT + tq];
                        dst[0]  = __float2half(v0);
                        dst[TT] = __float2half(v1);
                    }
                }
            }
        }
    }
}

// ---------------------------------------------------------------------------
// Flash attention: fp16 mma + ldmatrix, P in registers, ex2.f16x2 softmax,
// 1 barrier/tile; lp shfl-reduction deferred past PV MMA issue.
// 256 thr, 128 q-rows/CTA, K-tile 64. grid (BB*HQ, TT/128).
// ---------------------------------------------------------------------------
#define AST 36
#define KTW (64 * AST)
#define ATTN_SMEM ((4 * KTW) * 4)

__global__ __launch_bounds__(256, 2)
void attn_mma()
{
    extern __shared__ __align__(16) uint32_t dsm[];
    uint32_t* sK = dsm;
    uint32_t* sV = dsm + 2 * KTW;

    const int tid = threadIdx.x, lane = tid & 31, g = lane >> 2, t = lane & 3;
    const int bh  = blockIdx.x, b = bh >> 4, h = bh & 15, hk = h >> 2;
    const int qt  = blockIdx.y * 128;
    const int w   = tid >> 5;
    const int r0  = w * 16 + g;

    const int rselB = (lane & 7) + ((lane >> 4) & 1) * 8;
    const int cselB = ((lane >> 3) & 1) * 16;

    const __half* Qb = g_qh  + (((size_t)bh * TT + qt) << 6);
    const __half* Kb = g_kh  + (((size_t)(b * HKV + hk) * TT) << 6);
    const __half* Vb = g_vth + ((size_t)(b * HKV + hk) * HD) * TT;

    uint32_t qf[4][4];
#pragma unroll
    for (int ks = 0; ks < 4; ks++) {
        qf[ks][0] = *(const uint32_t*)(Qb + (size_t)r0 * 64 + (ks * 8 + t) * 2);
        qf[ks][1] = *(const uint32_t*)(Qb + (size_t)(r0 + 8) * 64 + (ks * 8 + t) * 2);
        qf[ks][2] = *(const uint32_t*)(Qb + (size_t)r0 * 64 + (ks * 8 + t + 4) * 2);
        qf[ks][3] = *(const uint32_t*)(Qb + (size_t)(r0 + 8) * 64 + (ks * 8 + t + 4) * 2);
    }

    const uint32_t smK = smem_u32(sK), smV = smem_u32(sV);

    auto load_tile = [&](int kt, int st) {
        const uint32_t kb = smK + st * KTW * 4, vb = smV + st * KTW * 4;
#pragma unroll
        for (int i = 0; i < 2; i++) {
            int c = tid + i * 256;
            int rr = c >> 3, off = c & 7;
            cpa16(kb + rr * (AST * 4) + off * 16,
                  Kb + (size_t)(kt + rr) * 64 + off * 8);
            cpa16(vb + rr * (AST * 4) + off * 16,
                  Vb + (size_t)rr * TT + kt + off * 8);
        }
    };

    float o[8][4] = {};
    float m0 = -3.0e38f, m1 = -3.0e38f, l0 = 0.f, l1 = 0.f;

    load_tile(0, 0);
    CP_COMMIT();

    const int NIT = TT / 64;
    for (int it = 0; it < NIT; it++) {
        const int cur = it & 1;
        CP_WAIT0();
        __syncthreads();
        if (it + 1 < NIT) { load_tile((it + 1) * 64, cur ^ 1); CP_COMMIT(); }

        const uint32_t smKc = smK + cur * KTW * 4;
        const uint32_t smVc = smV + cur * KTW * 4;

        // S = Q @ K^T (log2 domain)
        float s[8][4] = {};
#pragma unroll
        for (int nfp = 0; nfp < 8; nfp += 2) {
            const uint32_t ka = smKc + (nfp * 8 + rselB) * (AST * 4) + cselB;
#pragma unroll
            for (int ks = 0; ks < 4; ks++) {
                uint32_t bf[4];
                ldm4(bf, ka + ks * 32);
                mma16(s[nfp],     qf[ks], bf);
                mma16(s[nfp + 1], qf[ks], bf + 2);
            }
        }

        // online softmax
        float tm0 = -3.0e38f, tm1 = -3.0e38f;
#pragma unroll
        for (int nf = 0; nf < 8; nf++) {
            tm0 = fmaxf(tm0, fmaxf(s[nf][0], s[nf][1]));
            tm1 = fmaxf(tm1, fmaxf(s[nf][2], s[nf][3]));
        }
        tm0 = fmaxf(tm0, __shfl_xor_sync(0xffffffffu, tm0, 1));
        tm0 = fmaxf(tm0, __shfl_xor_sync(0xffffffffu, tm0, 2));
        tm1 = fmaxf(tm1, __shfl_xor_sync(0xffffffffu, tm1, 1));
        tm1 = fmaxf(tm1, __shfl_xor_sync(0xffffffffu, tm1, 2));

        const float nm0 = fmaxf(m0, tm0), nm1 = fmaxf(m1, tm1);
        const float c0 = ex2(m0 - nm0), c1 = ex2(m1 - nm1);
        m0 = nm0; m1 = nm1;

        // P fragments in registers; local lp sums (shfl deferred)
        uint32_t af[4][4];
        float lp0 = 0.f, lp1 = 0.f;
#pragma unroll
        for (int ks = 0; ks < 4; ks++) {
            const int lo = 2 * ks, hi = 2 * ks + 1;
            af[ks][0] = ex2h2(packh2(s[lo][0] - nm0, s[lo][1] - nm0));
            af[ks][1] = ex2h2(packh2(s[lo][2] - nm1, s[lo][3] - nm1));
            af[ks][2] = ex2h2(packh2(s[hi][0] - nm0, s[hi][1] - nm0));
            af[ks][3] = ex2h2(packh2(s[hi][2] - nm1, s[hi][3] - nm1));
            float2 f;
            f = __half22float2(*(__half2*)&af[ks][0]); lp0 += f.x + f.y;
            f = __half22float2(*(__half2*)&af[ks][2]); lp0 += f.x + f.y;
            f = __half22float2(*(__half2*)&af[ks][1]); lp1 += f.x + f.y;
            f = __half22float2(*(__half2*)&af[ks][3]); lp1 += f.x + f.y;
        }

#pragma unroll
        for (int nf = 0; nf < 8; nf++) {
            o[nf][0] *= c0; o[nf][1] *= c0;
            o[nf][2] *= c1; o[nf][3] *= c1;
        }

        // O += P @ V
#pragma unroll
        for (int nfp = 0; nfp < 8; nfp += 2) {
            const uint32_t va = smVc + (nfp * 8 + rselB) * (AST * 4) + cselB;
#pragma unroll
            for (int ks = 0; ks < 4; ks++) {
                uint32_t bf[4];
                ldm4(bf, va + ks * 32);
                mma16(o[nfp],     af[ks], bf);
                mma16(o[nfp + 1], af[ks], bf + 2);
            }
        }

        // deferred l reduction (hidden behind MMA latency)
        lp0 += __shfl_xor_sync(0xffffffffu, lp0, 1);
        lp0 += __shfl_xor_sync(0xffffffffu, lp0, 2);
        lp1 += __shfl_xor_sync(0xffffffffu, lp1, 1);
        lp1 += __shfl_xor_sync(0xffffffffu, lp1, 2);
        l0 = l0 * c0 + lp0;
        l1 = l1 * c1 + lp1;
    }

    const float i0 = 1.f / l0, i1 = 1.f / l1;
    const int tr = qt + r0;
#pragma unroll
    for (int nf = 0; nf < 8; nf++) {
        const int d = nf * 8 + 2 * t;
        *(uint32_t*)&g_aoh[((size_t)(b * TT + tr)     * DM) + h * 64 + d] =
            packh2(o[nf][0] * i0, o[nf][1] * i0);
        *(uint32_t*)&g_aoh[((size_t)(b * TT + tr + 8) * DM) + h * 64 + d] =
            packh2(o[nf][2] * i1, o[nf][3] * i1);
    }
}

// ---------------------------------------------------------------------------
extern "C" void kernel_launch(void* const* d_in, const int* in_sizes, int n_in,
                              void* d_out, int out_size)
{
    const float* x    = (const float*)d_in[0];
    const float* cosb = (const float*)d_in[1];
    const float* sinb = (const float*)d_in[2];
    const float* Wq   = (const float*)d_in[3];
    const float* Wkv  = (const float*)d_in[4];
    const float* Wo   = (const float*)d_in[5];
    float* out = (float*)d_out;

    __half *p_xh = nullptr, *p_wqt = nullptr, *p_wkvt = nullptr,
           *p_wot = nullptr, *p_aoh = nullptr;
    cudaGetSymbolAddress((void**)&p_xh,  g_xh);
    cudaGetSymbolAddress((void**)&p_wqt, g_wqt);
    cudaGetSymbolAddress((void**)&p_wkvt,g_wkvt);
    cudaGetSymbolAddress((void**)&p_wot, g_wot);
    cudaGetSymbolAddress((void**)&p_aoh, g_aoh);

    cudaFuncSetAttribute(attn_mma, cudaFuncAttributeMaxDynamicSharedMemorySize,
                         ATTN_SMEM);
    cudaFuncSetAttribute(tcmm<0>, cudaFuncAttributeMaxDynamicSharedMemorySize,
                         GEMM_SMEM);
    cudaFuncSetAttribute(tcmm<1>, cudaFuncAttributeMaxDynamicSharedMemorySize,
                         GEMM_SMEM);
    cudaFuncSetAttribute(tcmm<2>, cudaFuncAttributeMaxDynamicSharedMemorySize,
                         GEMM_SMEM);

    // Prep: x -> fp16; all W -> transposed fp16 (single launch)
    cvt_fp16<<<(MROWS * DM) / (256 * 4), 256>>>(x, p_xh, MROWS * DM);
    {
        dim3 grid(DM / 32, DM / 32, 3), blk(32, 8);
        trW3<<<grid, blk>>>(Wq, Wkv, Wo, p_wqt, p_wkvt, p_wot);
    }

    {   // Q projection + RoPE (+softmax scale)
        dim3 grid(DM / 128, MROWS / 128);
        tcmm<1><<<grid, 256, GEMM_SMEM>>>(p_xh, p_wqt, nullptr, DM, DM,
                                          cosb, sinb);
    }
    {   // KV projection + split (K RoPE, V transpose)
        dim3 grid((2 * HKV * HD) / 128, MROWS / 128);
        tcmm<2><<<grid, 256, GEMM_SMEM>>>(p_xh, p_wkvt, nullptr, 2 * HKV * HD,
                                          DM, cosb, sinb);
    }
    {   // attention
        dim3 grid(BB * HQ, TT / 128);
        attn_mma<<<grid, 256, ATTN_SMEM>>>();
    }
    {   // output projection
        dim3 grid(DM / 128, MROWS / 128);
        tcmm<0><<<grid, 256, GEMM_SMEM>>>(p_aoh, p_wot, out, DM, DM,
                                          nullptr, nullptr);
    }
}

// round 10
// speedup vs baseline: 9.2078x; 1.0058x over previous
#include <cuda_runtime.h>
#include <cuda_fp16.h>
#include <cstdint>

#define BB    4
#define TT    2048
#define DM    1024
#define HQ    16
#define HKV   4
#define HD    64
#define MROWS (BB*TT)

#define SCQ 0.1803368801111204f         // 0.125 * log2(e)

// fp16 scratch (device globals)
__device__ __half g_xh  [MROWS*DM];
__device__ __half g_wqt [DM*DM];            // Wq^T  [n][k]
__device__ __half g_wkvt[(2*HKV*HD)*DM];    // Wkv^T [n][k]
__device__ __half g_wot [DM*DM];            // Wo^T  [n][k]
__device__ __half g_qh  [BB*HQ *TT*HD];     // (b*HQ+h, t, d), pre-scaled SCQ
__device__ __half g_kh  [BB*HKV*TT*HD];     // (b*HKV+hk, t, d)
__device__ __half g_vth [BB*HKV*HD*TT];     // (b*HKV+hk, d, t)
__device__ __half g_aoh [BB*TT*DM];         // (b, t, h*64+d)

// ---------------------------------------------------------------------------
__device__ __forceinline__ float ex2(float x) {
    float r; asm("ex2.approx.f32 %0, %1;" : "=f"(r) : "f"(x)); return r;
}
__device__ __forceinline__ uint32_t ex2h2(uint32_t x) {
    uint32_t r; asm("ex2.approx.f16x2 %0, %1;" : "=r"(r) : "r"(x)); return r;
}
__device__ __forceinline__ uint32_t smem_u32(const void* p) {
    return (uint32_t)__cvta_generic_to_shared(p);
}
__device__ __forceinline__ void cpa16(uint32_t dst, const void* src) {
    asm volatile("cp.async.cg.shared.global [%0], [%1], 16;"
                 :: "r"(dst), "l"(src));
}
#define CP_COMMIT() asm volatile("cp.async.commit_group;" ::: "memory")
#define CP_WAIT1()  asm volatile("cp.async.wait_group 1;" ::: "memory")
#define CP_WAIT0()  asm volatile("cp.async.wait_group 0;" ::: "memory")

__device__ __forceinline__ void ldm4(uint32_t* r, uint32_t addr) {
    asm volatile("ldmatrix.sync.aligned.m8n8.x4.shared.b16 {%0,%1,%2,%3}, [%4];"
                 : "=r"(r[0]), "=r"(r[1]), "=r"(r[2]), "=r"(r[3]) : "r"(addr));
}
__device__ __forceinline__ void mma16(float* d, const uint32_t* a, const uint32_t* b) {
    asm volatile(
        "mma.sync.aligned.m16n8k16.row.col.f32.f16.f16.f32 "
        "{%0,%1,%2,%3}, {%4,%5,%6,%7}, {%8,%9}, {%0,%1,%2,%3};"
        : "+f"(d[0]), "+f"(d[1]), "+f"(d[2]), "+f"(d[3])
        : "r"(a[0]), "r"(a[1]), "r"(a[2]), "r"(a[3]), "r"(b[0]), "r"(b[1]));
}
__device__ __forceinline__ uint32_t packh2(float a, float b) {
    __half2 h = __floats2half2_rn(a, b);
    return *(uint32_t*)&h;
}

// ---------------------------------------------------------------------------
// Prep kernels
// ---------------------------------------------------------------------------
__global__ __launch_bounds__(256)
void cvt_fp16(const float* __restrict__ src, __half* __restrict__ dst, int n)
{
    int i = (blockIdx.x * 256 + threadIdx.x) * 4;
    if (i < n) {
        float4 v = *(const float4*)(src + i);
        uint2 o = {packh2(v.x, v.y), packh2(v.z, v.w)};
        *(uint2*)(dst + i) = o;
    }
}

// All three W transposes in one launch. blockIdx.z: 0=Wq, 1=Wkv, 2=Wo.
__global__ __launch_bounds__(256)
void trW3(const float* __restrict__ Wq, const float* __restrict__ Wkv,
          const float* __restrict__ Wo,
          __half* __restrict__ wqt, __half* __restrict__ wkvt,
          __half* __restrict__ wot)
{
    const float* W; __half* Wt; int N;
    if (blockIdx.z == 0)      { W = Wq;  Wt = wqt;  N = DM; }
    else if (blockIdx.z == 1) { W = Wkv; Wt = wkvt; N = 2 * HKV * HD; }
    else                      { W = Wo;  Wt = wot;  N = DM; }
    const int n0 = blockIdx.x * 32;
    if (n0 >= N) return;
    const int k0 = blockIdx.y * 32;

    __shared__ float tile[32][33];
#pragma unroll
    for (int i = threadIdx.y; i < 32; i += 8)
        tile[i][threadIdx.x] = W[(size_t)(k0 + i) * N + n0 + threadIdx.x];
    __syncthreads();
#pragma unroll
    for (int i = threadIdx.y; i < 32; i += 8)
        Wt[(size_t)(n0 + i) * DM + k0 + threadIdx.x] =
            __float2half(tile[threadIdx.x][i]);
}

// ---------------------------------------------------------------------------
// GEMM core: 128x128 tile, BK=64, 256 thr, 2(M)x4(N) warps, ldmatrix,
// 3-stage cp.async pipeline (steady-state wait_group 1).
// ---------------------------------------------------------------------------
#define GST 36                               // words per smem row (64h + pad)
#define GTW (128 * GST)                      // words per A-or-B tile stage
#define GEMM_SMEM ((6 * GTW) * 4)            // 3 stages x (A,B)

struct GemmCore {
    uint32_t smBase;
    const __half* A;
    const __half* Wt;
    int K, bm, bn, tid;
    int rselA, cselA, rselB, cselB, wm, wn;

    __device__ __forceinline__ void load_tile(int kt, int st) {
        const uint32_t ab = smBase + st * 2 * GTW * 4;
        const uint32_t bb = ab + GTW * 4;
#pragma unroll
        for (int i = 0; i < 4; i++) {
            int c = tid + i * 256;
            int rr = c >> 3, off = c & 7;
            cpa16(ab + rr * (GST * 4) + off * 16,
                  A + (size_t)(bm + rr) * K + kt + off * 8);
            cpa16(bb + rr * (GST * 4) + off * 16,
                  Wt + (size_t)(bn + rr) * K + kt + off * 8);
        }
    }

    __device__ __forceinline__ void run(float acc[4][4][4]) {
        load_tile(0, 0);  CP_COMMIT();
        load_tile(64, 1); CP_COMMIT();
        const int NIT = K / 64;
        for (int it = 0; it < NIT; it++) {
            if (it + 1 < NIT) CP_WAIT1(); else CP_WAIT0();
            __syncthreads();
            if (it + 2 < NIT) {
                int st = it + 2; st -= (st >= 3) ? 3 : 0; st -= (st >= 3) ? 3 : 0;
                load_tile((it + 2) * 64, (it + 2) % 3);
                CP_COMMIT();
            }
            const int cur = it % 3;
            const uint32_t smAc = smBase + cur * 2 * GTW * 4;
            const uint32_t smBc = smAc + GTW * 4;
#pragma unroll
            for (int ks = 0; ks < 4; ks++) {
                uint32_t af[4][4];
#pragma unroll
                for (int mf = 0; mf < 4; mf++)
                    ldm4(af[mf], smAc + (wm * 64 + mf * 16 + rselA) * (GST * 4)
                                   + cselA + ks * 32);
#pragma unroll
                for (int nfp = 0; nfp < 4; nfp += 2) {
                    uint32_t bf[4];
                    ldm4(bf, smBc + (wn * 32 + nfp * 8 + rselB) * (GST * 4)
                               + cselB + ks * 32);
#pragma unroll
                    for (int mf = 0; mf < 4; mf++) {
                        mma16(acc[mf][nfp],     af[mf], bf);
                        mma16(acc[mf][nfp + 1], af[mf], bf + 2);
                    }
                }
            }
        }
    }
};

__device__ __forceinline__ void gemm_init(GemmCore& gc, const __half* A,
                                          const __half* Wt, int K, int bm,
                                          int bn, uint32_t smBase)
{
    const int tid = threadIdx.x, lane = tid & 31;
    gc.smBase = smBase; gc.A = A; gc.Wt = Wt; gc.K = K;
    gc.bm = bm; gc.bn = bn; gc.tid = tid;
    gc.wm = (tid >> 5) >> 2; gc.wn = (tid >> 5) & 3;
    gc.rselA = (lane & 7) + ((lane >> 3) & 1) * 8;
    gc.cselA = ((lane >> 4) & 1) * 16;
    gc.rselB = (lane & 7) + ((lane >> 4) & 1) * 8;
    gc.cselB = ((lane >> 3) & 1) * 16;
}

// ---------------------------------------------------------------------------
// Fused Q + KV projection. grid (12, 64): bx 0-7 -> Q tiles, 8-11 -> KV.
// ---------------------------------------------------------------------------
__global__ __launch_bounds__(256, 2)
void tcmm_qkv(const __half* __restrict__ A, const __half* __restrict__ wqt,
              const __half* __restrict__ wkvt,
              const float* __restrict__ cosb, const float* __restrict__ sinb)
{
    extern __shared__ __align__(16) uint32_t gsm[];
    const bool isQ = blockIdx.x < 8;
    const int  bn  = (isQ ? blockIdx.x : blockIdx.x - 8) * 128;
    const int  bm  = blockIdx.y * 128;

    GemmCore gc;
    gemm_init(gc, A, isQ ? wqt : wkvt, DM, bm, bn, smem_u32(gsm));

    float acc[4][4][4] = {};
    gc.run(acc);

    const int lane = threadIdx.x & 31, g = lane >> 2, t = lane & 3;
    const int wid  = threadIdx.x >> 5, wm = wid >> 2, wn = wid & 3;

#pragma unroll
    for (int mf = 0; mf < 4; mf++) {
#pragma unroll
        for (int half = 0; half < 2; half++) {
            const int r  = bm + wm * 64 + mf * 16 + g + half * 8;
            const int bq = r >> 11, tq = r & (TT - 1);
#pragma unroll
            for (int nf = 0; nf < 4; nf++) {
                const float v0 = acc[mf][nf][half * 2];
                const float v1 = acc[mf][nf][half * 2 + 1];
                const int col = bn + wn * 32 + nf * 8 + 2 * t;
                if (isQ) {
                    const int h = col >> 6, d = col & 63;
                    const float c  = cosb[tq * HD + d];
                    const float sn = sinb[tq * HD + d];
                    uint32_t p = packh2((v0 * c - v1 * sn) * SCQ,
                                        (v1 * c + v0 * sn) * SCQ);
                    *(uint32_t*)&g_qh[(((size_t)(bq * HQ + h) * TT + tq) << 6) + d] = p;
                } else {
                    const int hk = col >> 7, pair = (col >> 6) & 1, d = col & 63;
                    if (pair == 0) {
                        const float c  = cosb[tq * HD + d];
                        const float sn = sinb[tq * HD + d];
                        uint32_t p = packh2(v0 * c - v1 * sn, v1 * c + v0 * sn);
                        *(uint32_t*)&g_kh[(((size_t)(bq * HKV + hk) * TT + tq) << 6) + d] = p;
                    } else {
                        __half* dst = &g_vth[((size_t)(bq * HKV + hk) * HD + d) * TT + tq];
                        dst[0]  = __float2half(v0);
                        dst[TT] = __float2half(v1);
                    }
                }
            }
        }
    }
}

// ---------------------------------------------------------------------------
// Output projection: C = Ao @ Wo, plain fp32 store.
// ---------------------------------------------------------------------------
__global__ __launch_bounds__(256, 2)
void tcmm_o(const __half* __restrict__ A, const __half* __restrict__ Wt,
            float* __restrict__ C)
{
    extern __shared__ __align__(16) uint32_t gsm[];
    const int bm = blockIdx.y * 128, bn = blockIdx.x * 128;

    GemmCore gc;
    gemm_init(gc, A, Wt, DM, bm, bn, smem_u32(gsm));

    float acc[4][4][4] = {};
    gc.run(acc);

    const int lane = threadIdx.x & 31, g = lane >> 2, t = lane & 3;
    const int wid  = threadIdx.x >> 5, wm = wid >> 2, wn = wid & 3;

#pragma unroll
    for (int mf = 0; mf < 4; mf++)
#pragma unroll
        for (int half = 0; half < 2; half++) {
            const int r = bm + wm * 64 + mf * 16 + g + half * 8;
#pragma unroll
            for (int nf = 0; nf < 4; nf++) {
                const int col = bn + wn * 32 + nf * 8 + 2 * t;
                float2 o = {acc[mf][nf][half * 2], acc[mf][nf][half * 2 + 1]};
                *(float2*)(C + (size_t)r * DM + col) = o;
            }
        }
}

// ---------------------------------------------------------------------------
// Flash attention: fp16 mma + ldmatrix, P in registers, ex2.f16x2 softmax,
// 3-stage cp.async pipeline, 1 barrier/tile, deferred l reduction.
// 256 thr, 128 q-rows/CTA, K-tile 64. grid (BB*HQ, TT/128).
// ---------------------------------------------------------------------------
#define AST 36
#define KTW (64 * AST)                  // words per K-or-V tile stage
#define ATTN_SMEM ((6 * KTW) * 4)       // 3 stages x (K,V)

__global__ __launch_bounds__(256, 2)
void attn_mma()
{
    extern __shared__ __align__(16) uint32_t dsm[];

    const int tid = threadIdx.x, lane = tid & 31, g = lane >> 2, t = lane & 3;
    const int bh  = blockIdx.x, b = bh >> 4, h = bh & 15, hk = h >> 2;
    const int qt  = blockIdx.y * 128;
    const int w   = tid >> 5;
    const int r0  = w * 16 + g;

    const int rselB = (lane & 7) + ((lane >> 4) & 1) * 8;
    const int cselB = ((lane >> 3) & 1) * 16;

    const __half* Qb = g_qh  + (((size_t)bh * TT + qt) << 6);
    const __half* Kb = g_kh  + (((size_t)(b * HKV + hk) * TT) << 6);
    const __half* Vb = g_vth + ((size_t)(b * HKV + hk) * HD) * TT;

    uint32_t qf[4][4];
#pragma unroll
    for (int ks = 0; ks < 4; ks++) {
        qf[ks][0] = *(const uint32_t*)(Qb + (size_t)r0 * 64 + (ks * 8 + t) * 2);
        qf[ks][1] = *(const uint32_t*)(Qb + (size_t)(r0 + 8) * 64 + (ks * 8 + t) * 2);
        qf[ks][2] = *(const uint32_t*)(Qb + (size_t)r0 * 64 + (ks * 8 + t + 4) * 2);
        qf[ks][3] = *(const uint32_t*)(Qb + (size_t)(r0 + 8) * 64 + (ks * 8 + t + 4) * 2);
    }

    const uint32_t smBase = smem_u32(dsm);

    auto load_tile = [&](int kt, int st) {
        const uint32_t kb = smBase + st * 2 * KTW * 4;
        const uint32_t vb = kb + KTW * 4;
#pragma unroll
        for (int i = 0; i < 2; i++) {
            int c = tid + i * 256;
            int rr = c >> 3, off = c & 7;
            cpa16(kb + rr * (AST * 4) + off * 16,
                  Kb + (size_t)(kt + rr) * 64 + off * 8);
            cpa16(vb + rr * (AST * 4) + off * 16,
                  Vb + (size_t)rr * TT + kt + off * 8);
        }
    };

    float o[8][4] = {};
    float m0 = -3.0e38f, m1 = -3.0e38f, l0 = 0.f, l1 = 0.f;

    load_tile(0, 0);  CP_COMMIT();
    load_tile(64, 1); CP_COMMIT();

    const int NIT = TT / 64;
    for (int it = 0; it < NIT; it++) {
        if (it + 1 < NIT) CP_WAIT1(); else CP_WAIT0();
        __syncthreads();
        if (it + 2 < NIT) { load_tile((it + 2) * 64, (it + 2) % 3); CP_COMMIT(); }

        const int cur = it % 3;
        const uint32_t smKc = smBase + cur * 2 * KTW * 4;
        const uint32_t smVc = smKc + KTW * 4;

        // S = Q @ K^T (log2 domain)
        float s[8][4] = {};
#pragma unroll
        for (int nfp = 0; nfp < 8; nfp += 2) {
            const uint32_t ka = smKc + (nfp * 8 + rselB) * (AST * 4) + cselB;
#pragma unroll
            for (int ks = 0; ks < 4; ks++) {
                uint32_t bf[4];
                ldm4(bf, ka + ks * 32);
                mma16(s[nfp],     qf[ks], bf);
                mma16(s[nfp + 1], qf[ks], bf + 2);
            }
        }

        // online softmax
        float tm0 = -3.0e38f, tm1 = -3.0e38f;
#pragma unroll
        for (int nf = 0; nf < 8; nf++) {
            tm0 = fmaxf(tm0, fmaxf(s[nf][0], s[nf][1]));
            tm1 = fmaxf(tm1, fmaxf(s[nf][2], s[nf][3]));
        }
        tm0 = fmaxf(tm0, __shfl_xor_sync(0xffffffffu, tm0, 1));
        tm0 = fmaxf(tm0, __shfl_xor_sync(0xffffffffu, tm0, 2));
        tm1 = fmaxf(tm1, __shfl_xor_sync(0xffffffffu, tm1, 1));
        tm1 = fmaxf(tm1, __shfl_xor_sync(0xffffffffu, tm1, 2));

        const float nm0 = fmaxf(m0, tm0), nm1 = fmaxf(m1, tm1);
        const float c0 = ex2(m0 - nm0), c1 = ex2(m1 - nm1);
        m0 = nm0; m1 = nm1;

        uint32_t af[4][4];
        float lp0 = 0.f, lp1 = 0.f;
#pragma unroll
        for (int ks = 0; ks < 4; ks++) {
            const int lo = 2 * ks, hi = 2 * ks + 1;
            af[ks][0] = ex2h2(packh2(s[lo][0] - nm0, s[lo][1] - nm0));
            af[ks][1] = ex2h2(packh2(s[lo][2] - nm1, s[lo][3] - nm1));
            af[ks][2] = ex2h2(packh2(s[hi][0] - nm0, s[hi][1] - nm0));
            af[ks][3] = ex2h2(packh2(s[hi][2] - nm1, s[hi][3] - nm1));
            float2 f;
            f = __half22float2(*(__half2*)&af[ks][0]); lp0 += f.x + f.y;
            f = __half22float2(*(__half2*)&af[ks][2]); lp0 += f.x + f.y;
            f = __half22float2(*(__half2*)&af[ks][1]); lp1 += f.x + f.y;
            f = __half22float2(*(__half2*)&af[ks][3]); lp1 += f.x + f.y;
        }

#pragma unroll
        for (int nf = 0; nf < 8; nf++) {
            o[nf][0] *= c0; o[nf][1] *= c0;
            o[nf][2] *= c1; o[nf][3] *= c1;
        }

        // O += P @ V
#pragma unroll
        for (int nfp = 0; nfp < 8; nfp += 2) {
            const uint32_t va = smVc + (nfp * 8 + rselB) * (AST * 4) + cselB;
#pragma unroll
            for (int ks = 0; ks < 4; ks++) {
                uint32_t bf[4];
                ldm4(bf, va + ks * 32);
                mma16(o[nfp],     af[ks], bf);
                mma16(o[nfp + 1], af[ks], bf + 2);
            }
        }

        // deferred l reduction (hidden behind MMA latency)
        lp0 += __shfl_xor_sync(0xffffffffu, lp0, 1);
        lp0 += __shfl_xor_sync(0xffffffffu, lp0, 2);
        lp1 += __shfl_xor_sync(0xffffffffu, lp1, 1);
        lp1 += __shfl_xor_sync(0xffffffffu, lp1, 2);
        l0 = l0 * c0 + lp0;
        l1 = l1 * c1 + lp1;
    }

    const float i0 = 1.f / l0, i1 = 1.f / l1;
    const int tr = qt + r0;
#pragma unroll
    for (int nf = 0; nf < 8; nf++) {
        const int d = nf * 8 + 2 * t;
        *(uint32_t*)&g_aoh[((size_t)(b * TT + tr)     * DM) + h * 64 + d] =
            packh2(o[nf][0] * i0, o[nf][1] * i0);
        *(uint32_t*)&g_aoh[((size_t)(b * TT + tr + 8) * DM) + h * 64 + d] =
            packh2(o[nf][2] * i1, o[nf][3] * i1);
    }
}

// ---------------------------------------------------------------------------
extern "C" void kernel_launch(void* const* d_in, const int* in_sizes, int n_in,
                              void* d_out, int out_size)
{
    const float* x    = (const float*)d_in[0];
    const float* cosb = (const float*)d_in[1];
    const float* sinb = (const float*)d_in[2];
    const float* Wq   = (const float*)d_in[3];
    const float* Wkv  = (const float*)d_in[4];
    const float* Wo   = (const float*)d_in[5];
    float* out = (float*)d_out;

    __half *p_xh = nullptr, *p_wqt = nullptr, *p_wkvt = nullptr,
           *p_wot = nullptr, *p_aoh = nullptr;
    cudaGetSymbolAddress((void**)&p_xh,  g_xh);
    cudaGetSymbolAddress((void**)&p_wqt, g_wqt);
    cudaGetSymbolAddress((void**)&p_wkvt,g_wkvt);
    cudaGetSymbolAddress((void**)&p_wot, g_wot);
    cudaGetSymbolAddress((void**)&p_aoh, g_aoh);

    cudaFuncSetAttribute(attn_mma, cudaFuncAttributeMaxDynamicSharedMemorySize,
                         ATTN_SMEM);
    cudaFuncSetAttribute(tcmm_qkv, cudaFuncAttributeMaxDynamicSharedMemorySize,
                         GEMM_SMEM);
    cudaFuncSetAttribute(tcmm_o, cudaFuncAttributeMaxDynamicSharedMemorySize,
                         GEMM_SMEM);

    // Prep: x -> fp16; all W -> transposed fp16 (single launch)
    cvt_fp16<<<(MROWS * DM) / (256 * 4), 256>>>(x, p_xh, MROWS * DM);
    {
        dim3 grid(DM / 32, DM / 32, 3), blk(32, 8);
        trW3<<<grid, blk>>>(Wq, Wkv, Wo, p_wqt, p_wkvt, p_wot);
    }

    {   // fused Q + KV projection (+RoPE, split, V transpose)
        dim3 grid(12, MROWS / 128);
        tcmm_qkv<<<grid, 256, GEMM_SMEM>>>(p_xh, p_wqt, p_wkvt, cosb, sinb);
    }
    {   // attention
        dim3 grid(BB * HQ, TT / 128);
        attn_mma<<<grid, 256, ATTN_SMEM>>>();
    }
    {   // output projection
        dim3 grid(DM / 128, MROWS / 128);
        tcmm_o<<<grid, 256, GEMM_SMEM>>>(p_aoh, p_wot, out);
    }
}